// round 13
// baseline (speedup 1.0000x reference)
#include <cuda_runtime.h>
#include <cuda_bf16.h>
#include <cstdint>

// ---------------- constants ----------------
#define NB      8
#define CI      256
#define HW      1600
#define DM      128
#define NHEAD   8
#define DH      16
#define NROWS   (NB*HW)        // 12800
#define NCLOUD  32768

// ---------------- device scratch ----------------
__device__ float g_tok [NROWS*DM];     // l2-normalized image tokens
__device__ float g_attn[NROWS*DM];     // attention output
__device__ float g_m0  [NB*DM];        // per (b, dim) sum of normalized tokens
__device__ float g_imgacc[NB*CI];
__device__ float g_seg  [NB*DM];
__device__ float g_cnt  [NB];

typedef unsigned long long u64;

// ---------------- packed f32x2 helpers ----------------
__device__ __forceinline__ u64 fma2(u64 a, u64 b, u64 c){
  u64 d; asm("fma.rn.f32x2 %0, %1, %2, %3;" : "=l"(d) : "l"(a), "l"(b), "l"(c)); return d;
}
__device__ __forceinline__ u64 mul2(u64 a, u64 b){
  u64 d; asm("mul.rn.f32x2 %0, %1, %2;" : "=l"(d) : "l"(a), "l"(b)); return d;
}
__device__ __forceinline__ u64 add2(u64 a, u64 b){
  u64 d; asm("add.rn.f32x2 %0, %1, %2;" : "=l"(d) : "l"(a), "l"(b)); return d;
}
__device__ __forceinline__ u64 pack2(float x, float y){
  u64 d; asm("mov.b64 %0, {%1, %2};" : "=l"(d) : "f"(x), "f"(y)); return d;
}
__device__ __forceinline__ float2 unpack2(u64 u){
  float2 f; asm("mov.b64 {%0, %1}, %2;" : "=f"(f.x), "=f"(f.y) : "l"(u)); return f;
}

__device__ __forceinline__ uint32_t cvt_bf16x2(u64 p){
  float2 f = unpack2(p);
  uint32_t r;
  asm("cvt.rn.bf16x2.f32 %0, %1, %2;" : "=r"(r) : "f"(f.y), "f"(f.x));
  return r;
}
__device__ __forceinline__ uint32_t cvt_bf16x2_ff(float lo, float hi){
  uint32_t r;
  asm("cvt.rn.bf16x2.f32 %0, %1, %2;" : "=r"(r) : "f"(hi), "f"(lo));
  return r;
}
__device__ __forceinline__ uint32_t packbf(__nv_bfloat16 a, __nv_bfloat16 b){
  __nv_bfloat162 t(a, b);
  return *reinterpret_cast<uint32_t*>(&t);
}

// ---------------- mma / ldmatrix helpers ----------------
__device__ __forceinline__ void mma_bf16(float* c, const uint32_t* a, uint32_t b0, uint32_t b1){
  asm volatile("mma.sync.aligned.m16n8k16.row.col.f32.bf16.bf16.f32 "
      "{%0,%1,%2,%3}, {%4,%5,%6,%7}, {%8,%9}, {%0,%1,%2,%3};"
      : "+f"(c[0]), "+f"(c[1]), "+f"(c[2]), "+f"(c[3])
      : "r"(a[0]), "r"(a[1]), "r"(a[2]), "r"(a[3]), "r"(b0), "r"(b1));
}
__device__ __forceinline__ void ldsm4(uint32_t addr, uint32_t* r){
  asm volatile("ldmatrix.sync.aligned.m8n8.x4.shared.b16 {%0,%1,%2,%3}, [%4];"
      : "=r"(r[0]), "=r"(r[1]), "=r"(r[2]), "=r"(r[3]) : "r"(addr));
}
__device__ __forceinline__ void ldsm4t(uint32_t addr, uint32_t* r){
  asm volatile("ldmatrix.sync.aligned.m8n8.x4.trans.shared.b16 {%0,%1,%2,%3}, [%4];"
      : "=r"(r[0]), "=r"(r[1]), "=r"(r[2]), "=r"(r[3]) : "r"(addr));
}
__device__ __forceinline__ void sts64(uint32_t addr, uint32_t r0, uint32_t r1){
  asm volatile("st.shared.v2.b32 [%0], {%1,%2};" :: "r"(addr), "r"(r0), "r"(r1));
}

// split pair of floats to hi/lo bf16x2
__device__ __forceinline__ void split2(float x0, float x1, uint32_t& hi, uint32_t& lo){
  __nv_bfloat16 h0 = __float2bfloat16_rn(x0);
  __nv_bfloat16 h1 = __float2bfloat16_rn(x1);
  float r0 = x0 - __bfloat162float(h0);
  float r1 = x1 - __bfloat162float(h1);
  hi = packbf(h0, h1);
  lo = packbf(__float2bfloat16_rn(r0), __float2bfloat16_rn(r1));
}

// ---------------- K0: zero accumulators ----------------
__global__ void zero_kernel(){
  int i = blockIdx.x*256 + threadIdx.x;
  if (i < NB*CI) g_imgacc[i] = 0.f;
  if (i < NB*DM){ g_seg[i] = 0.f; g_m0[i] = 0.f; }
  if (i < NB)    g_cnt[i]  = 0.f;
}

// ---------------- K1: gemm1 via split-bf16 mma + l2norm + M0 fusion ----------
__global__ __launch_bounds__(256, 2) void gemm1_mma_kernel(const float* __restrict__ img,
                                                           const float* __restrict__ W1,
                                                           const float* __restrict__ b1){
  __shared__ __align__(128) unsigned char sAh[2048];
  __shared__ __align__(128) unsigned char sAl[2048];
  __shared__ __align__(128) unsigned char sWh[4096];
  __shared__ __align__(128) unsigned char sWl[4096];
  __shared__ __align__(16)  float sOut[64*132];
  int tile = blockIdx.x;
  int b = tile / 25, pbase = (tile % 25) * 64;
  int tid = threadIdx.x, w = tid >> 5, lane = tid & 31;
  int gid = lane >> 2, tig = lane & 3, r7 = lane & 7;

  uint32_t ah0 = (uint32_t)__cvta_generic_to_shared(sAh);
  uint32_t al0 = (uint32_t)__cvta_generic_to_shared(sAl);
  uint32_t wh0 = (uint32_t)__cvta_generic_to_shared(sWh);
  uint32_t wl0 = (uint32_t)__cvta_generic_to_shared(sWl);

  const float* Abase = img + b*CI*HW + pbase;

  float oa[8][4];
  #pragma unroll
  for (int i=0;i<8;i++){ oa[i][0]=0.f; oa[i][1]=0.f; oa[i][2]=0.f; oa[i][3]=0.f; }

  int kkA = r7 + ((lane >> 4) & 1)*8;
  int uA  = (w & 3)*2 + ((lane >> 3) & 1);
  uint32_t aoff = (uint32_t)(kkA*128 + ((uA ^ (kkA & 7)))*16);
  int kkW = r7 + ((lane >> 3) & 1)*8;
  int nsel = (lane >> 4) & 1;
  int nbase8 = (w >> 2)*8;

  int kkSa = tid >> 4, r4 = tid & 15;
  int kkSw = tid >> 5, c4 = tid & 31;
  int ncw = c4 >> 1, halfw = c4 & 1;
  uint32_t aSaddr  = (uint32_t)(kkSa*128 + (((r4 >> 1) ^ (kkSa & 7)))*16 + (r4 & 1)*8);
  uint32_t wSaddr0 = (uint32_t)(kkSw*256 + ((ncw ^ (kkSw & 7)))*16 + halfw*8);
  uint32_t wSaddr1 = (uint32_t)((kkSw+8)*256 + ((ncw ^ ((kkSw+8) & 7)))*16 + halfw*8);

  for (int ks=0; ks<16; ks++){
    float4 va  = *(const float4*)(Abase + (ks*16 + kkSa)*HW + r4*4);
    float4 vw0 = *(const float4*)(W1 + (ks*16 + kkSw)*DM + c4*4);
    float4 vw1 = *(const float4*)(W1 + (ks*16 + 8 + kkSw)*DM + c4*4);
    __syncthreads();
    {
      uint32_t h0,l0,h1,l1;
      split2(va.x, va.y, h0, l0); split2(va.z, va.w, h1, l1);
      sts64(ah0 + aSaddr, h0, h1);
      sts64(al0 + aSaddr, l0, l1);
      split2(vw0.x, vw0.y, h0, l0); split2(vw0.z, vw0.w, h1, l1);
      sts64(wh0 + wSaddr0, h0, h1);
      sts64(wl0 + wSaddr0, l0, l1);
      split2(vw1.x, vw1.y, h0, l0); split2(vw1.z, vw1.w, h1, l1);
      sts64(wh0 + wSaddr1, h0, h1);
      sts64(wl0 + wSaddr1, l0, l1);
    }
    __syncthreads();

    uint32_t ah[4], al[4];
    ldsm4t(ah0 + aoff, ah);
    ldsm4t(al0 + aoff, al);

    #pragma unroll
    for (int p=0; p<4; p++){
      int unit = nbase8 + 2*p + nsel;
      uint32_t waddr = (uint32_t)(kkW*256 + ((unit ^ (kkW & 7)))*16);
      uint32_t wh[4], wl[4];
      ldsm4t(wh0 + waddr, wh);
      ldsm4t(wl0 + waddr, wl);
      mma_bf16(oa[2*p],   ah, wh[0], wh[1]);
      mma_bf16(oa[2*p],   ah, wl[0], wl[1]);
      mma_bf16(oa[2*p],   al, wh[0], wh[1]);
      mma_bf16(oa[2*p+1], ah, wh[2], wh[3]);
      mma_bf16(oa[2*p+1], ah, wl[2], wl[3]);
      mma_bf16(oa[2*p+1], al, wh[2], wh[3]);
    }
  }
  __syncthreads();

  {
    int r0 = (w & 3)*16 + gid;
    #pragma unroll
    for (int p=0; p<8; p++){
      int c0 = (w >> 2)*64 + p*8 + 2*tig;
      sOut[r0*132 + c0]       = oa[p][0];
      sOut[r0*132 + c0 + 1]   = oa[p][1];
      sOut[(r0+8)*132 + c0]   = oa[p][2];
      sOut[(r0+8)*132 + c0+1] = oa[p][3];
    }
  }
  __syncthreads();

  {
    int r = tid >> 2, seg = tid & 3;
    float xv[32];
    float s = 0.f;
    float* op = sOut + r*132 + seg*32;
    const float* bp = b1 + seg*32;
    #pragma unroll
    for (int j4=0; j4<8; j4++){
      float4 xb = *(float4*)(op + j4*4);
      float4 bb = *(const float4*)(bp + j4*4);
      float x0 = xb.x + bb.x, x1 = xb.y + bb.y, x2 = xb.z + bb.z, x3 = xb.w + bb.w;
      xv[4*j4]=x0; xv[4*j4+1]=x1; xv[4*j4+2]=x2; xv[4*j4+3]=x3;
      s += x0*x0 + x1*x1 + x2*x2 + x3*x3;
    }
    s += __shfl_xor_sync(0xffffffffu, s, 1);
    s += __shfl_xor_sync(0xffffffffu, s, 2);
    float inv = 1.0f / fmaxf(sqrtf(s), 1e-12f);
    float* tp = g_tok + (size_t)(tile*64 + r)*DM + seg*32;
    #pragma unroll
    for (int j4=0; j4<8; j4++){
      float4 o = make_float4(xv[4*j4]*inv, xv[4*j4+1]*inv, xv[4*j4+2]*inv, xv[4*j4+3]*inv);
      *(float4*)(tp + j4*4) = o;
      *(float4*)(op + j4*4) = o;
    }
  }
  __syncthreads();

  if (tid < 128){
    float cs = 0.f;
    #pragma unroll 8
    for (int r=0; r<64; r++) cs += sOut[r*132 + tid];
    atomicAdd(&g_m0[b*DM + tid], cs);
  }
}

// ---------------- K3: attention, 32 queries/warp (2 independent qsets) -------
__global__ __launch_bounds__(128) void attn_bf16_kernel(){
  __shared__ __align__(1024) unsigned char sbuf[2][2048];
  int b = blockIdx.z, h = blockIdx.y;
  int tid = threadIdx.x, w = tid >> 5, lane = tid & 31;
  int gid = lane >> 2, tig = lane & 3, r7 = lane & 7;
  const float* base = g_tok + b*HW*DM + h*DH;
  int qb0 = blockIdx.x*128 + w*32;
  int qs0 = qb0, qs1 = qb0 + 16;
  bool st0 = (qs0 < HW), st1 = (qs1 < HW);
  if (!st0) qs0 = HW - 16;
  if (!st1) qs1 = HW - 16;

  // ---- Q fragments for both qsets (scaled by 0.25), plain bf16 ----
  uint32_t qh0[4], qh1[4];
  #pragma unroll
  for (int i=0;i<4;i++){
    int roff = gid + (i & 1)*8;
    int col = 2*tig + (i >> 1)*8;
    float2 v0 = *(const float2*)(base + (qs0+roff)*DM + col);
    float2 v1 = *(const float2*)(base + (qs1+roff)*DM + col);
    qh0[i] = packbf(__float2bfloat16_rn(v0.x*0.25f), __float2bfloat16_rn(v0.y*0.25f));
    qh1[i] = packbf(__float2bfloat16_rn(v1.x*0.25f), __float2bfloat16_rn(v1.y*0.25f));
  }

  float oa00[4] = {0.f,0.f,0.f,0.f};   // qset0, dims 0-7
  float oa01[4] = {0.f,0.f,0.f,0.f};   // qset0, dims 8-15
  float oa10[4] = {0.f,0.f,0.f,0.f};   // qset1, dims 0-7
  float oa11[4] = {0.f,0.f,0.f,0.f};   // qset1, dims 8-15
  u64 l0A01=0ULL, l0A23=0ULL, l0B01=0ULL, l0B23=0ULL;
  u64 l1A01=0ULL, l1A23=0ULL, l1B01=0ULL, l1B23=0ULL;

  const u64 C24 = pack2(4.1666667e-2f, 4.1666667e-2f);
  const u64 C6  = pack2(1.6666667e-1f, 1.6666667e-1f);
  const u64 CH  = pack2(0.5f, 0.5f);
  const u64 C1  = pack2(1.0f, 1.0f);

  uint32_t sb0 = (uint32_t)__cvta_generic_to_shared(&sbuf[0][0]);
  uint32_t aScore = sb0 + (uint32_t)((r7 + ((lane >> 4) & 1)*8)*16 + ((lane >> 3) & 1)*1024);
  uint32_t aPV    = sb0 + (uint32_t)((r7 + ((lane >> 3) & 1)*8)*16 + ((lane >> 4) & 1)*1024);

  // ---- tile loads: 128 threads x 2 float4 ----
  int keyA = tid >> 1, qA = (tid & 1)*2;      // quarters 0/2
  int keyB = keyA,     qB = qA + 1;           // quarters 1/3
  const float* gsrcA = base + keyA*DM + qA*4;
  const float* gsrcB = base + keyB*DM + qB*4;
  uint32_t dstA = sb0 + (uint32_t)((qA >> 1)*1024 + keyA*16 + (qA & 1)*8);
  uint32_t dstB = sb0 + (uint32_t)((qB >> 1)*1024 + keyB*16 + (qB & 1)*8);

  {
    float4 vA = *(const float4*)(gsrcA);
    float4 vB = *(const float4*)(gsrcB);
    sts64(dstA, cvt_bf16x2_ff(vA.x, vA.y), cvt_bf16x2_ff(vA.z, vA.w));
    sts64(dstB, cvt_bf16x2_ff(vB.x, vB.y), cvt_bf16x2_ff(vB.z, vB.w));
  }
  __syncthreads();

  for (int kb=0; kb<25; kb++){
    float4 nvA, nvB;
    if (kb < 24){
      nvA = *(const float4*)(gsrcA + (kb+1)*64*DM);
      nvB = *(const float4*)(gsrcB + (kb+1)*64*DM);
    }
    uint32_t bufoff = (uint32_t)((kb & 1)*2048);
    uint32_t aS = aScore + bufoff;
    uint32_t aP = aPV + bufoff;

    #pragma unroll
    for (int ck=0; ck<4; ck++){
      uint32_t off = (uint32_t)(ck*256);
      uint32_t kh[4], vv[4];
      ldsm4 (aS + off, kh);
      ldsm4t(aP + off, vv);

      float c0A[4] = {0.f,0.f,0.f,0.f};
      float c0B[4] = {0.f,0.f,0.f,0.f};
      float c1A[4] = {0.f,0.f,0.f,0.f};
      float c1B[4] = {0.f,0.f,0.f,0.f};
      mma_bf16(c0A, qh0, kh[0], kh[1]);
      mma_bf16(c1A, qh1, kh[0], kh[1]);
      mma_bf16(c0B, qh0, kh[2], kh[3]);
      mma_bf16(c1B, qh1, kh[2], kh[3]);

      u64 t0A01 = pack2(c0A[0], c0A[1]);
      u64 t0A23 = pack2(c0A[2], c0A[3]);
      u64 t0B01 = pack2(c0B[0], c0B[1]);
      u64 t0B23 = pack2(c0B[2], c0B[3]);
      u64 t1A01 = pack2(c1A[0], c1A[1]);
      u64 t1A23 = pack2(c1A[2], c1A[3]);
      u64 t1B01 = pack2(c1B[0], c1B[1]);
      u64 t1B23 = pack2(c1B[2], c1B[3]);

      u64 w0A01 = fma2(t0A01, C24, C6);
      u64 w0A23 = fma2(t0A23, C24, C6);
      u64 w0B01 = fma2(t0B01, C24, C6);
      u64 w0B23 = fma2(t0B23, C24, C6);
      u64 w1A01 = fma2(t1A01, C24, C6);
      u64 w1A23 = fma2(t1A23, C24, C6);
      u64 w1B01 = fma2(t1B01, C24, C6);
      u64 w1B23 = fma2(t1B23, C24, C6);
      w0A01 = fma2(t0A01, w0A01, CH);  w0A23 = fma2(t0A23, w0A23, CH);
      w0B01 = fma2(t0B01, w0B01, CH);  w0B23 = fma2(t0B23, w0B23, CH);
      w1A01 = fma2(t1A01, w1A01, CH);  w1A23 = fma2(t1A23, w1A23, CH);
      w1B01 = fma2(t1B01, w1B01, CH);  w1B23 = fma2(t1B23, w1B23, CH);
      w0A01 = fma2(t0A01, w0A01, C1);  w0A23 = fma2(t0A23, w0A23, C1);
      w0B01 = fma2(t0B01, w0B01, C1);  w0B23 = fma2(t0B23, w0B23, C1);
      w1A01 = fma2(t1A01, w1A01, C1);  w1A23 = fma2(t1A23, w1A23, C1);
      w1B01 = fma2(t1B01, w1B01, C1);  w1B23 = fma2(t1B23, w1B23, C1);
      u64 u0A01 = mul2(t0A01, w0A01);
      u64 u0A23 = mul2(t0A23, w0A23);
      u64 u0B01 = mul2(t0B01, w0B01);
      u64 u0B23 = mul2(t0B23, w0B23);
      u64 u1A01 = mul2(t1A01, w1A01);
      u64 u1A23 = mul2(t1A23, w1A23);
      u64 u1B01 = mul2(t1B01, w1B01);
      u64 u1B23 = mul2(t1B23, w1B23);
      l0A01 = add2(l0A01, u0A01);
      l0A23 = add2(l0A23, u0A23);
      l0B01 = add2(l0B01, u0B01);
      l0B23 = add2(l0B23, u0B23);
      l1A01 = add2(l1A01, u1A01);
      l1A23 = add2(l1A23, u1A23);
      l1B01 = add2(l1B01, u1B01);
      l1B23 = add2(l1B23, u1B23);

      uint32_t pa0[4], pa1[4];
      pa0[0] = cvt_bf16x2(u0A01);
      pa0[1] = cvt_bf16x2(u0A23);
      pa0[2] = cvt_bf16x2(u0B01);
      pa0[3] = cvt_bf16x2(u0B23);
      pa1[0] = cvt_bf16x2(u1A01);
      pa1[1] = cvt_bf16x2(u1A23);
      pa1[2] = cvt_bf16x2(u1B01);
      pa1[3] = cvt_bf16x2(u1B23);

      mma_bf16(oa00, pa0, vv[0], vv[1]);
      mma_bf16(oa10, pa1, vv[0], vv[1]);
      mma_bf16(oa01, pa0, vv[2], vv[3]);
      mma_bf16(oa11, pa1, vv[2], vv[3]);
    }

    if (kb < 24){
      uint32_t dA = dstA + (uint32_t)(((kb+1) & 1)*2048);
      uint32_t dB = dstB + (uint32_t)(((kb+1) & 1)*2048);
      sts64(dA, cvt_bf16x2_ff(nvA.x, nvA.y), cvt_bf16x2_ff(nvA.z, nvA.w));
      sts64(dB, cvt_bf16x2_ff(nvB.x, nvB.y), cvt_bf16x2_ff(nvB.z, nvB.w));
    }
    __syncthreads();
  }

  // ---- epilogue per qset ----
  const float* m0p = g_m0 + b*DM + h*DH;
  {
    float2 fA01 = unpack2(l0A01), fA23 = unpack2(l0A23);
    float2 fB01 = unpack2(l0B01), fB23 = unpack2(l0B23);
    float lr0 = fA01.x + fA01.y + fB01.x + fB01.y;
    float lr8 = fA23.x + fA23.y + fB23.x + fB23.y;
    lr0 += __shfl_xor_sync(0xffffffffu, lr0, 1);
    lr0 += __shfl_xor_sync(0xffffffffu, lr0, 2);
    lr8 += __shfl_xor_sync(0xffffffffu, lr8, 1);
    lr8 += __shfl_xor_sync(0xffffffffu, lr8, 2);
    float inv0 = 1.0f / (1600.0f + lr0);
    float inv8 = 1.0f / (1600.0f + lr8);
    if (st0){
      float* outb = g_attn + (b*HW + qs0)*DM + h*DH;
      float* oas[2] = {oa00, oa01};
      #pragma unroll
      for (int nt=0; nt<2; nt++){
        int d0 = nt*8 + 2*tig;
        float m0a = m0p[d0], m0b = m0p[d0+1];
        outb[(gid  )*DM + d0    ] = (oas[nt][0] + m0a) * inv0;
        outb[(gid  )*DM + d0 + 1] = (oas[nt][1] + m0b) * inv0;
        outb[(gid+8)*DM + d0    ] = (oas[nt][2] + m0a) * inv8;
        outb[(gid+8)*DM + d0 + 1] = (oas[nt][3] + m0b) * inv8;
      }
    }
  }
  {
    float2 fA01 = unpack2(l1A01), fA23 = unpack2(l1A23);
    float2 fB01 = unpack2(l1B01), fB23 = unpack2(l1B23);
    float lr0 = fA01.x + fA01.y + fB01.x + fB01.y;
    float lr8 = fA23.x + fA23.y + fB23.x + fB23.y;
    lr0 += __shfl_xor_sync(0xffffffffu, lr0, 1);
    lr0 += __shfl_xor_sync(0xffffffffu, lr0, 2);
    lr8 += __shfl_xor_sync(0xffffffffu, lr8, 1);
    lr8 += __shfl_xor_sync(0xffffffffu, lr8, 2);
    float inv0 = 1.0f / (1600.0f + lr0);
    float inv8 = 1.0f / (1600.0f + lr8);
    if (st1){
      float* outb = g_attn + (b*HW + qs1)*DM + h*DH;
      float* oas[2] = {oa10, oa11};
      #pragma unroll
      for (int nt=0; nt<2; nt++){
        int d0 = nt*8 + 2*tig;
        float m0a = m0p[d0], m0b = m0p[d0+1];
        outb[(gid  )*DM + d0    ] = (oas[nt][0] + m0a) * inv0;
        outb[(gid  )*DM + d0 + 1] = (oas[nt][1] + m0b) * inv0;
        outb[(gid+8)*DM + d0    ] = (oas[nt][2] + m0a) * inv8;
        outb[(gid+8)*DM + d0 + 1] = (oas[nt][3] + m0b) * inv8;
      }
    }
  }
}

// ---------------- K4: gemm2 via split-bf16 mma, N split across 2 CTAs --------
__global__ __launch_bounds__(256, 2) void gemm2_mma_kernel(const float* __restrict__ W2,
                                                           const float* __restrict__ b2,
                                                           float* __restrict__ img_out){
  __shared__ __align__(1024) unsigned char sA[2][16384];   // hi/lo planes
  __shared__ __align__(1024) unsigned char sW[2][4096];    // hi/lo planes (16k x 128n stage)
  int tile = blockIdx.x, nh = blockIdx.y;
  int b = tile / 25, pbase = (tile % 25) * 64;
  int tid = threadIdx.x, w = tid >> 5, lane = tid & 31;
  int gid = lane >> 2, tig = lane & 3, r7 = lane & 7;

  uint32_t sa0 = (uint32_t)__cvta_generic_to_shared(&sA[0][0]);
  uint32_t sw0 = (uint32_t)__cvta_generic_to_shared(&sW[0][0]);

  {
    const float* Abase = g_attn + (size_t)(tile*64)*DM;
    #pragma unroll
    for (int it=0; it<8; it++){
      int idx = tid + it*256;
      int r = idx >> 5, kc4 = idx & 31;
      int kc = kc4 >> 1, half = kc4 & 1;
      float4 v = *(const float4*)(Abase + r*DM + kc4*4);
      uint32_t h0, l0, h1, l1;
      split2(v.x, v.y, h0, l0);
      split2(v.z, v.w, h1, l1);
      uint32_t addr = sa0 + (uint32_t)(r*256 + ((kc ^ (r & 7)))*16 + half*8);
      sts64(addr,         h0, h1);
      sts64(addr + 16384, l0, l1);
    }
  }

  float oa[8][4];
  #pragma unroll
  for (int i=0;i<8;i++){ oa[i][0]=0.f; oa[i][1]=0.f; oa[i][2]=0.f; oa[i][3]=0.f; }

  int arow = (w & 3)*16 + r7 + ((lane >> 3) & 1)*8;
  int klocal = r7 + ((lane >> 3) & 1)*8;
  int ncsel  = (lane >> 4) & 1;
  int nbase  = (w >> 2) * 8;            // 8 n-units of 8 cols per warp-half

  for (int ks=0; ks<8; ks++){
    // prefetch W stage (16 k x 128 n f32) into regs: 512 float4 / 256 thr = 2 each
    float4 wreg[2];
    #pragma unroll
    for (int it=0; it<2; it++){
      int idx = tid + it*256;
      int kk = idx >> 5, nc4 = idx & 31;
      wreg[it] = *(const float4*)(W2 + (ks*16 + kk)*CI + nh*128 + nc4*4);
    }
    __syncthreads();
    #pragma unroll
    for (int it=0; it<2; it++){
      int idx = tid + it*256;
      int kk = idx >> 5, nc4 = idx & 31;
      int nc = nc4 >> 1, half = nc4 & 1;
      uint32_t h0, l0, h1, l1;
      split2(wreg[it].x, wreg[it].y, h0, l0);
      split2(wreg[it].z, wreg[it].w, h1, l1);
      uint32_t addr = sw0 + (uint32_t)(kk*256 + (nc ^ (kk & 7))*16 + half*8);
      sts64(addr,        h0, h1);
      sts64(addr + 4096, l0, l1);
    }
    __syncthreads();

    uint32_t ah[4], al[4];
    {
      int kcv = 2*ks + ((lane >> 4) & 1);
      uint32_t aaddr = sa0 + (uint32_t)(arow*256 + ((kcv ^ r7))*16);
      ldsm4(aaddr, ah);
      ldsm4(aaddr + 16384, al);
    }

    #pragma unroll
    for (int p=0; p<4; p++){
      int nc0 = nbase + 2*p;
      uint32_t waddr = sw0 + (uint32_t)(klocal*256 + (((nc0 + ncsel) ^ r7))*16);
      uint32_t wh[4], wl[4];
      ldsm4t(waddr, wh);
      ldsm4t(waddr + 4096, wl);
      mma_bf16(oa[2*p],   ah, wh[0], wh[1]);
      mma_bf16(oa[2*p],   ah, wl[0], wl[1]);
      mma_bf16(oa[2*p],   al, wh[0], wh[1]);
      mma_bf16(oa[2*p+1], ah, wh[2], wh[3]);
      mma_bf16(oa[2*p+1], ah, wl[2], wl[3]);
      mma_bf16(oa[2*p+1], al, wh[2], wh[3]);
    }
  }

  int p0 = pbase + (w & 3)*16 + gid;
  float* outB = img_out + (size_t)b*CI*HW;
  #pragma unroll
  for (int nc=0; nc<8; nc++){
    int c0 = nh*128 + (w >> 2)*64 + nc*8 + 2*tig;
    float bb0 = __ldg(b2 + c0), bb1 = __ldg(b2 + c0 + 1);
    float v00 = oa[nc][0] + bb0, v01 = oa[nc][1] + bb1;
    float v10 = oa[nc][2] + bb0, v11 = oa[nc][3] + bb1;
    outB[(size_t)c0*HW + p0]           = v00;
    outB[(size_t)(c0+1)*HW + p0]       = v01;
    outB[(size_t)c0*HW + p0 + 8]       = v10;
    outB[(size_t)(c0+1)*HW + p0 + 8]   = v11;
    float e00 = fmaxf(v00, 1e-6f), e01 = fmaxf(v01, 1e-6f);
    float e10 = fmaxf(v10, 1e-6f), e11 = fmaxf(v11, 1e-6f);
    float pc0 = e00*e00*e00 + e10*e10*e10;
    float pc1 = e01*e01*e01 + e11*e11*e11;
    pc0 += __shfl_xor_sync(0xffffffffu, pc0, 4);
    pc1 += __shfl_xor_sync(0xffffffffu, pc1, 4);
    pc0 += __shfl_xor_sync(0xffffffffu, pc0, 8);
    pc1 += __shfl_xor_sync(0xffffffffu, pc1, 8);
    pc0 += __shfl_xor_sync(0xffffffffu, pc0, 16);
    pc1 += __shfl_xor_sync(0xffffffffu, pc1, 16);
    if (lane < 4){
      atomicAdd(&g_imgacc[b*CI + c0],     pc0);
      atomicAdd(&g_imgacc[b*CI + c0 + 1], pc1);
    }
  }
}

// ---------------- K7: cloud l2norm + segmented clamp^3 sum -------------------
__global__ __launch_bounds__(256) void cloud_kernel(const float* __restrict__ cf,
                                                    const int* __restrict__ bids,
                                                    float* __restrict__ cloud_out){
  __shared__ float sseg[NB*DM];
  __shared__ float scnt[NB];
  int tid = threadIdx.x;
  for (int i=tid; i<NB*DM; i+=256) sseg[i] = 0.f;
  if (tid < NB) scnt[tid] = 0.f;
  __syncthreads();
  int w = tid >> 5, lane = tid & 31;
  int rbase = blockIdx.x*64 + w*8;
  #pragma unroll
  for (int i=0;i<8;i++){
    int row = rbase + i;
    int bid = bids[row];
    float4 v = *(const float4*)(cf + row*DM + lane*4);
    float sq = v.x*v.x + v.y*v.y + v.z*v.z + v.w*v.w;
    #pragma unroll
    for (int off=16; off; off>>=1) sq += __shfl_xor_sync(0xffffffffu, sq, off);
    float inv = 1.0f / fmaxf(sqrtf(sq), 1e-12f);
    float x0=v.x*inv, x1=v.y*inv, x2=v.z*inv, x3=v.w*inv;
    *(float4*)(cloud_out + row*DM + lane*4) = make_float4(x0,x1,x2,x3);
    float c0=fmaxf(x0,1e-6f), c1=fmaxf(x1,1e-6f), c2=fmaxf(x2,1e-6f), c3=fmaxf(x3,1e-6f);
    float* sp = sseg + bid*DM + lane*4;
    atomicAdd(sp+0, c0*c0*c0);
    atomicAdd(sp+1, c1*c1*c1);
    atomicAdd(sp+2, c2*c2*c2);
    atomicAdd(sp+3, c3*c3*c3);
    if (lane == 0) atomicAdd(&scnt[bid], 1.0f);
  }
  __syncthreads();
  for (int i=tid; i<NB*DM; i+=256) atomicAdd(&g_seg[i], sseg[i]);
  if (tid < NB) atomicAdd(&g_cnt[tid], scnt[tid]);
}

// ---------------- K8: finalize GeM outputs ----------------
__global__ void finalize_kernel(float* __restrict__ image_gem, float* __restrict__ cloud_gem){
  int i = blockIdx.x*256 + threadIdx.x;
  if (i < NB*CI) image_gem[i] = cbrtf(g_imgacc[i] * (1.0f/1600.0f));
  if (i < NB*DM) cloud_gem[i] = cbrtf(g_seg[i] / fmaxf(g_cnt[i>>7], 1.0f));
}

// ---------------- launch ----------------
extern "C" void kernel_launch(void* const* d_in, const int* in_sizes, int n_in,
                              void* d_out, int out_size){
  const float* img  = (const float*)d_in[0];
  const float* cf   = (const float*)d_in[1];
  const int*   bids = (const int*)  d_in[2];
  const float* W1   = (const float*)d_in[3];
  const float* b1   = (const float*)d_in[4];
  const float* W2   = (const float*)d_in[5];
  const float* b2   = (const float*)d_in[6];

  float* out       = (float*)d_out;
  float* img_out   = out;                                  // 8*256*1600
  float* cloud_out = out + (size_t)NB*CI*HW;               // 32768*128
  float* image_gem = cloud_out + (size_t)NCLOUD*DM;        // 2048
  float* cloud_gem = image_gem + NB*CI;                    // 1024

  zero_kernel<<<8, 256>>>();
  gemm1_mma_kernel<<<200, 256>>>(img, W1, b1);
  attn_bf16_kernel<<<dim3(13, NHEAD, NB), 128>>>();
  gemm2_mma_kernel<<<dim3(200, 2), 256>>>(W2, b2, img_out);
  cloud_kernel<<<512, 256>>>(cf, bids, cloud_out);
  finalize_kernel<<<8, 256>>>(image_gem, cloud_gem);
}

// round 14
// speedup vs baseline: 1.0221x; 1.0221x over previous
#include <cuda_runtime.h>
#include <cuda_bf16.h>
#include <cstdint>

// ---------------- constants ----------------
#define NB      8
#define CI      256
#define HW      1600
#define DM      128
#define NHEAD   8
#define DH      16
#define NROWS   (NB*HW)        // 12800
#define NCLOUD  32768

// ---------------- device scratch ----------------
__device__ float g_tok [NROWS*DM];     // l2-normalized image tokens
__device__ float g_attn[NROWS*DM];     // attention output
__device__ float g_m0  [NB*DM];        // per (b, dim) sum of normalized tokens
__device__ float g_imgacc[NB*CI];
__device__ float g_seg  [NB*DM];
__device__ float g_cnt  [NB];

typedef unsigned long long u64;

// ---------------- packed f32x2 helpers ----------------
__device__ __forceinline__ u64 fma2(u64 a, u64 b, u64 c){
  u64 d; asm("fma.rn.f32x2 %0, %1, %2, %3;" : "=l"(d) : "l"(a), "l"(b), "l"(c)); return d;
}
__device__ __forceinline__ u64 mul2(u64 a, u64 b){
  u64 d; asm("mul.rn.f32x2 %0, %1, %2;" : "=l"(d) : "l"(a), "l"(b)); return d;
}
__device__ __forceinline__ u64 add2(u64 a, u64 b){
  u64 d; asm("add.rn.f32x2 %0, %1, %2;" : "=l"(d) : "l"(a), "l"(b)); return d;
}
__device__ __forceinline__ u64 pack2(float x, float y){
  u64 d; asm("mov.b64 %0, {%1, %2};" : "=l"(d) : "f"(x), "f"(y)); return d;
}
__device__ __forceinline__ float2 unpack2(u64 u){
  float2 f; asm("mov.b64 {%0, %1}, %2;" : "=f"(f.x), "=f"(f.y) : "l"(u)); return f;
}

__device__ __forceinline__ uint32_t cvt_bf16x2(u64 p){
  float2 f = unpack2(p);
  uint32_t r;
  asm("cvt.rn.bf16x2.f32 %0, %1, %2;" : "=r"(r) : "f"(f.y), "f"(f.x));
  return r;
}
__device__ __forceinline__ uint32_t cvt_bf16x2_ff(float lo, float hi){
  uint32_t r;
  asm("cvt.rn.bf16x2.f32 %0, %1, %2;" : "=r"(r) : "f"(hi), "f"(lo));
  return r;
}
__device__ __forceinline__ uint32_t packbf(__nv_bfloat16 a, __nv_bfloat16 b){
  __nv_bfloat162 t(a, b);
  return *reinterpret_cast<uint32_t*>(&t);
}

// ---------------- mma / ldmatrix helpers ----------------
__device__ __forceinline__ void mma_bf16(float* c, const uint32_t* a, uint32_t b0, uint32_t b1){
  asm volatile("mma.sync.aligned.m16n8k16.row.col.f32.bf16.bf16.f32 "
      "{%0,%1,%2,%3}, {%4,%5,%6,%7}, {%8,%9}, {%0,%1,%2,%3};"
      : "+f"(c[0]), "+f"(c[1]), "+f"(c[2]), "+f"(c[3])
      : "r"(a[0]), "r"(a[1]), "r"(a[2]), "r"(a[3]), "r"(b0), "r"(b1));
}
__device__ __forceinline__ void ldsm4(uint32_t addr, uint32_t* r){
  asm volatile("ldmatrix.sync.aligned.m8n8.x4.shared.b16 {%0,%1,%2,%3}, [%4];"
      : "=r"(r[0]), "=r"(r[1]), "=r"(r[2]), "=r"(r[3]) : "r"(addr));
}
__device__ __forceinline__ void ldsm4t(uint32_t addr, uint32_t* r){
  asm volatile("ldmatrix.sync.aligned.m8n8.x4.trans.shared.b16 {%0,%1,%2,%3}, [%4];"
      : "=r"(r[0]), "=r"(r[1]), "=r"(r[2]), "=r"(r[3]) : "r"(addr));
}
__device__ __forceinline__ void sts64(uint32_t addr, uint32_t r0, uint32_t r1){
  asm volatile("st.shared.v2.b32 [%0], {%1,%2};" :: "r"(addr), "r"(r0), "r"(r1));
}

// split pair of floats to hi/lo bf16x2
__device__ __forceinline__ void split2(float x0, float x1, uint32_t& hi, uint32_t& lo){
  __nv_bfloat16 h0 = __float2bfloat16_rn(x0);
  __nv_bfloat16 h1 = __float2bfloat16_rn(x1);
  float r0 = x0 - __bfloat162float(h0);
  float r1 = x1 - __bfloat162float(h1);
  hi = packbf(h0, h1);
  lo = packbf(__float2bfloat16_rn(r0), __float2bfloat16_rn(r1));
}

// ---------------- K0: zero accumulators ----------------
__global__ void zero_kernel(){
  int i = blockIdx.x*256 + threadIdx.x;
  if (i < NB*CI) g_imgacc[i] = 0.f;
  if (i < NB*DM){ g_seg[i] = 0.f; g_m0[i] = 0.f; }
  if (i < NB)    g_cnt[i]  = 0.f;
}

// ---------------- K1: gemm1 split-bf16 mma, double-buffered stages -----------
// x = img^T @ W1 + b1; 64 rows x 128 cols per CTA; 16 k-stages, 1 sync/stage.
__global__ __launch_bounds__(256, 2) void gemm1_mma_kernel(const float* __restrict__ img,
                                                           const float* __restrict__ W1,
                                                           const float* __restrict__ b1){
  __shared__ __align__(128) unsigned char sAh[2][2048];
  __shared__ __align__(128) unsigned char sAl[2][2048];
  __shared__ __align__(128) unsigned char sWh[2][4096];
  __shared__ __align__(128) unsigned char sWl[2][4096];
  __shared__ __align__(16)  float sOut[64*132];
  int tile = blockIdx.x;
  int b = tile / 25, pbase = (tile % 25) * 64;
  int tid = threadIdx.x, w = tid >> 5, lane = tid & 31;
  int gid = lane >> 2, tig = lane & 3, r7 = lane & 7;

  uint32_t ah0 = (uint32_t)__cvta_generic_to_shared(&sAh[0][0]);
  uint32_t al0 = (uint32_t)__cvta_generic_to_shared(&sAl[0][0]);
  uint32_t wh0 = (uint32_t)__cvta_generic_to_shared(&sWh[0][0]);
  uint32_t wl0 = (uint32_t)__cvta_generic_to_shared(&sWl[0][0]);

  const float* Abase = img + b*CI*HW + pbase;

  float oa[8][4];
  #pragma unroll
  for (int i=0;i<8;i++){ oa[i][0]=0.f; oa[i][1]=0.f; oa[i][2]=0.f; oa[i][3]=0.f; }

  int kkA = r7 + ((lane >> 4) & 1)*8;
  int uA  = (w & 3)*2 + ((lane >> 3) & 1);
  uint32_t aoff = (uint32_t)(kkA*128 + ((uA ^ (kkA & 7)))*16);
  int kkW = r7 + ((lane >> 3) & 1)*8;
  int nsel = (lane >> 4) & 1;
  int nbase8 = (w >> 2)*8;

  int kkSa = tid >> 4, r4 = tid & 15;
  int kkSw = tid >> 5, c4 = tid & 31;
  int ncw = c4 >> 1, halfw = c4 & 1;
  uint32_t aSaddr  = (uint32_t)(kkSa*128 + (((r4 >> 1) ^ (kkSa & 7)))*16 + (r4 & 1)*8);
  uint32_t wSaddr0 = (uint32_t)(kkSw*256 + ((ncw ^ (kkSw & 7)))*16 + halfw*8);
  uint32_t wSaddr1 = (uint32_t)((kkSw+8)*256 + ((ncw ^ ((kkSw+8) & 7)))*16 + halfw*8);

  // prologue: stage 0 -> buffer 0
  {
    float4 va  = *(const float4*)(Abase + (kkSa)*HW + r4*4);
    float4 vw0 = *(const float4*)(W1 + (kkSw)*DM + c4*4);
    float4 vw1 = *(const float4*)(W1 + (8 + kkSw)*DM + c4*4);
    uint32_t h0,l0,h1,l1;
    split2(va.x, va.y, h0, l0); split2(va.z, va.w, h1, l1);
    sts64(ah0 + aSaddr, h0, h1);
    sts64(al0 + aSaddr, l0, l1);
    split2(vw0.x, vw0.y, h0, l0); split2(vw0.z, vw0.w, h1, l1);
    sts64(wh0 + wSaddr0, h0, h1);
    sts64(wl0 + wSaddr0, l0, l1);
    split2(vw1.x, vw1.y, h0, l0); split2(vw1.z, vw1.w, h1, l1);
    sts64(wh0 + wSaddr1, h0, h1);
    sts64(wl0 + wSaddr1, l0, l1);
  }

  for (int ks=0; ks<16; ks++){
    float4 va, vw0, vw1;
    if (ks < 15){
      va  = *(const float4*)(Abase + ((ks+1)*16 + kkSa)*HW + r4*4);
      vw0 = *(const float4*)(W1 + ((ks+1)*16 + kkSw)*DM + c4*4);
      vw1 = *(const float4*)(W1 + ((ks+1)*16 + 8 + kkSw)*DM + c4*4);
    }
    __syncthreads();      // stage ks visible; reads of buf((ks+1)&1) from ks-1 done
    if (ks < 15){
      uint32_t bo = (uint32_t)(((ks+1) & 1));
      uint32_t h0,l0,h1,l1;
      split2(va.x, va.y, h0, l0); split2(va.z, va.w, h1, l1);
      sts64(ah0 + bo*2048 + aSaddr, h0, h1);
      sts64(al0 + bo*2048 + aSaddr, l0, l1);
      split2(vw0.x, vw0.y, h0, l0); split2(vw0.z, vw0.w, h1, l1);
      sts64(wh0 + bo*4096 + wSaddr0, h0, h1);
      sts64(wl0 + bo*4096 + wSaddr0, l0, l1);
      split2(vw1.x, vw1.y, h0, l0); split2(vw1.z, vw1.w, h1, l1);
      sts64(wh0 + bo*4096 + wSaddr1, h0, h1);
      sts64(wl0 + bo*4096 + wSaddr1, l0, l1);
    }

    uint32_t cu = (uint32_t)(ks & 1);
    uint32_t ah[4], al[4];
    ldsm4t(ah0 + cu*2048 + aoff, ah);
    ldsm4t(al0 + cu*2048 + aoff, al);

    #pragma unroll
    for (int p=0; p<4; p++){
      int unit = nbase8 + 2*p + nsel;
      uint32_t waddr = cu*4096 + (uint32_t)(kkW*256 + ((unit ^ (kkW & 7)))*16);
      uint32_t wh[4], wl[4];
      ldsm4t(wh0 + waddr, wh);
      ldsm4t(wl0 + waddr, wl);
      mma_bf16(oa[2*p],   ah, wh[0], wh[1]);
      mma_bf16(oa[2*p],   ah, wl[0], wl[1]);
      mma_bf16(oa[2*p],   al, wh[0], wh[1]);
      mma_bf16(oa[2*p+1], ah, wh[2], wh[3]);
      mma_bf16(oa[2*p+1], ah, wl[2], wl[3]);
      mma_bf16(oa[2*p+1], al, wh[2], wh[3]);
    }
  }
  __syncthreads();

  {
    int r0 = (w & 3)*16 + gid;
    #pragma unroll
    for (int p=0; p<8; p++){
      int c0 = (w >> 2)*64 + p*8 + 2*tig;
      sOut[r0*132 + c0]       = oa[p][0];
      sOut[r0*132 + c0 + 1]   = oa[p][1];
      sOut[(r0+8)*132 + c0]   = oa[p][2];
      sOut[(r0+8)*132 + c0+1] = oa[p][3];
    }
  }
  __syncthreads();

  {
    int r = tid >> 2, seg = tid & 3;
    float xv[32];
    float s = 0.f;
    float* op = sOut + r*132 + seg*32;
    const float* bp = b1 + seg*32;
    #pragma unroll
    for (int j4=0; j4<8; j4++){
      float4 xb = *(float4*)(op + j4*4);
      float4 bb = *(const float4*)(bp + j4*4);
      float x0 = xb.x + bb.x, x1 = xb.y + bb.y, x2 = xb.z + bb.z, x3 = xb.w + bb.w;
      xv[4*j4]=x0; xv[4*j4+1]=x1; xv[4*j4+2]=x2; xv[4*j4+3]=x3;
      s += x0*x0 + x1*x1 + x2*x2 + x3*x3;
    }
    s += __shfl_xor_sync(0xffffffffu, s, 1);
    s += __shfl_xor_sync(0xffffffffu, s, 2);
    float inv = 1.0f / fmaxf(sqrtf(s), 1e-12f);
    float* tp = g_tok + (size_t)(tile*64 + r)*DM + seg*32;
    #pragma unroll
    for (int j4=0; j4<8; j4++){
      float4 o = make_float4(xv[4*j4]*inv, xv[4*j4+1]*inv, xv[4*j4+2]*inv, xv[4*j4+3]*inv);
      *(float4*)(tp + j4*4) = o;
      *(float4*)(op + j4*4) = o;
    }
  }
  __syncthreads();

  if (tid < 128){
    float cs = 0.f;
    #pragma unroll 8
    for (int r=0; r<64; r++) cs += sOut[r*132 + tid];
    atomicAdd(&g_m0[b*DM + tid], cs);
  }
}

// ---------------- K3: attention (R12 structure), deg-3 expm1 -----------------
__global__ __launch_bounds__(256) void attn_bf16_kernel(){
  __shared__ __align__(1024) unsigned char sbuf[2][2048];
  int b = blockIdx.z, h = blockIdx.y;
  int tid = threadIdx.x, w = tid >> 5, lane = tid & 31;
  int gid = lane >> 2, tig = lane & 3;
  const float* base = g_tok + b*HW*DM + h*DH;
  int qb0 = blockIdx.x*128 + w*16;
  bool wstore = (qb0 < HW);
  int qbase = wstore ? qb0 : (HW - 16);

  uint32_t qh[4];
  #pragma unroll
  for (int i=0;i<4;i++){
    int row = qbase + gid + (i & 1)*8;
    int col = 2*tig + (i >> 1)*8;
    float2 v = *(const float2*)(base + row*DM + col);
    qh[i] = packbf(__float2bfloat16_rn(v.x*0.25f), __float2bfloat16_rn(v.y*0.25f));
  }

  float oa0E[4] = {0.f,0.f,0.f,0.f};
  float oa1E[4] = {0.f,0.f,0.f,0.f};
  float oa0O[4] = {0.f,0.f,0.f,0.f};
  float oa1O[4] = {0.f,0.f,0.f,0.f};
  u64 lA01 = 0ULL, lA23 = 0ULL, lB01 = 0ULL, lB23 = 0ULL;

  const u64 C6  = pack2(1.6666667e-1f, 1.6666667e-1f);
  const u64 CH  = pack2(0.5f, 0.5f);
  const u64 C1  = pack2(1.0f, 1.0f);

  uint32_t sb0 = (uint32_t)__cvta_generic_to_shared(&sbuf[0][0]);
  int r7 = lane & 7;
  uint32_t aScore = sb0 + (uint32_t)((r7 + ((lane >> 4) & 1)*8)*16 + ((lane >> 3) & 1)*1024);
  uint32_t aPV    = sb0 + (uint32_t)((r7 + ((lane >> 3) & 1)*8)*16 + ((lane >> 4) & 1)*1024);

  int key = tid >> 2, quarter = tid & 3;
  const float* gsrc = base + key*DM + quarter*4;
  uint32_t dstK = sb0 + (uint32_t)((quarter >> 1)*1024 + key*16 + (quarter & 1)*8);

  {
    float4 v = *(const float4*)(gsrc);
    sts64(dstK, cvt_bf16x2_ff(v.x, v.y), cvt_bf16x2_ff(v.z, v.w));
  }
  __syncthreads();

  for (int kb=0; kb<25; kb++){
    float4 nv;
    if (kb < 24) nv = *(const float4*)(gsrc + (kb+1)*64*DM);
    uint32_t bufoff = (uint32_t)((kb & 1)*2048);
    uint32_t aS = aScore + bufoff;
    uint32_t aP = aPV + bufoff;

    #pragma unroll
    for (int ck=0; ck<4; ck++){
      uint32_t off = (uint32_t)(ck*256);
      uint32_t kh[4], vv[4];
      ldsm4 (aS + off, kh);
      ldsm4t(aP + off, vv);

      float cA[4] = {0.f,0.f,0.f,0.f};
      float cB[4] = {0.f,0.f,0.f,0.f};
      mma_bf16(cA, qh, kh[0], kh[1]);
      mma_bf16(cB, qh, kh[2], kh[3]);

      // u = expm1(t), deg-3, packed pairs
      u64 tA01 = pack2(cA[0], cA[1]);
      u64 tA23 = pack2(cA[2], cA[3]);
      u64 tB01 = pack2(cB[0], cB[1]);
      u64 tB23 = pack2(cB[2], cB[3]);
      u64 wA01 = fma2(tA01, C6, CH);
      u64 wA23 = fma2(tA23, C6, CH);
      u64 wB01 = fma2(tB01, C6, CH);
      u64 wB23 = fma2(tB23, C6, CH);
      wA01 = fma2(tA01, wA01, C1);  wA23 = fma2(tA23, wA23, C1);
      wB01 = fma2(tB01, wB01, C1);  wB23 = fma2(tB23, wB23, C1);
      u64 uA01 = mul2(tA01, wA01);
      u64 uA23 = mul2(tA23, wA23);
      u64 uB01 = mul2(tB01, wB01);
      u64 uB23 = mul2(tB23, wB23);
      lA01 = add2(lA01, uA01);
      lA23 = add2(lA23, uA23);
      lB01 = add2(lB01, uB01);
      lB23 = add2(lB23, uB23);

      uint32_t pa[4];
      pa[0] = cvt_bf16x2(uA01);
      pa[1] = cvt_bf16x2(uA23);
      pa[2] = cvt_bf16x2(uB01);
      pa[3] = cvt_bf16x2(uB23);

      if (ck & 1){
        mma_bf16(oa0O, pa, vv[0], vv[1]);
        mma_bf16(oa1O, pa, vv[2], vv[3]);
      } else {
        mma_bf16(oa0E, pa, vv[0], vv[1]);
        mma_bf16(oa1E, pa, vv[2], vv[3]);
      }
    }

    if (kb < 24){
      uint32_t d = dstK + (uint32_t)(((kb+1) & 1)*2048);
      sts64(d, cvt_bf16x2_ff(nv.x, nv.y), cvt_bf16x2_ff(nv.z, nv.w));
    }
    __syncthreads();
  }

  float oa0[4], oa1[4];
  #pragma unroll
  for (int i=0;i<4;i++){ oa0[i] = oa0E[i] + oa0O[i]; oa1[i] = oa1E[i] + oa1O[i]; }
  float2 fA01 = unpack2(lA01), fA23 = unpack2(lA23);
  float2 fB01 = unpack2(lB01), fB23 = unpack2(lB23);
  float lr0 = fA01.x + fA01.y + fB01.x + fB01.y;
  float lr8 = fA23.x + fA23.y + fB23.x + fB23.y;
  lr0 += __shfl_xor_sync(0xffffffffu, lr0, 1);
  lr0 += __shfl_xor_sync(0xffffffffu, lr0, 2);
  lr8 += __shfl_xor_sync(0xffffffffu, lr8, 1);
  lr8 += __shfl_xor_sync(0xffffffffu, lr8, 2);
  float inv0 = 1.0f / (1600.0f + lr0);
  float inv8 = 1.0f / (1600.0f + lr8);

  if (wstore){
    const float* m0p = g_m0 + b*DM + h*DH;
    float* outb = g_attn + (b*HW + qbase)*DM + h*DH;
    float* oas[2] = {oa0, oa1};
    #pragma unroll
    for (int nt=0; nt<2; nt++){
      int d0 = nt*8 + 2*tig;
      float m0a = m0p[d0], m0b = m0p[d0+1];
      outb[(gid  )*DM + d0    ] = (oas[nt][0] + m0a) * inv0;
      outb[(gid  )*DM + d0 + 1] = (oas[nt][1] + m0b) * inv0;
      outb[(gid+8)*DM + d0    ] = (oas[nt][2] + m0a) * inv8;
      outb[(gid+8)*DM + d0 + 1] = (oas[nt][3] + m0b) * inv8;
    }
  }
}

// ---------------- K4: gemm2 split-bf16 mma, double-buffered W stage ----------
// 64 rows x 256 cols per CTA (R12 tiling), 8 k-stages, 1 sync/stage.
__global__ __launch_bounds__(256, 2) void gemm2_mma_kernel(const float* __restrict__ W2,
                                                           const float* __restrict__ b2,
                                                           float* __restrict__ img_out){
  __shared__ __align__(1024) unsigned char sA[2][16384];     // hi/lo planes (A, single)
  __shared__ __align__(1024) unsigned char sW[2][16384];     // 2 stages x (hi 8K + lo 8K)
  int tile = blockIdx.x;
  int b = tile / 25, pbase = (tile % 25) * 64;
  int tid = threadIdx.x, w = tid >> 5, lane = tid & 31;
  int gid = lane >> 2, tig = lane & 3, r7 = lane & 7;

  uint32_t sa0 = (uint32_t)__cvta_generic_to_shared(&sA[0][0]);
  uint32_t sw0 = (uint32_t)__cvta_generic_to_shared(&sW[0][0]);

  // ---- A tile load + split-store (single buffer) ----
  {
    const float* Abase = g_attn + (size_t)(tile*64)*DM;
    #pragma unroll
    for (int it=0; it<8; it++){
      int idx = tid + it*256;
      int r = idx >> 5, kc4 = idx & 31;
      int kc = kc4 >> 1, half = kc4 & 1;
      float4 v = *(const float4*)(Abase + r*DM + kc4*4);
      uint32_t h0, l0, h1, l1;
      split2(v.x, v.y, h0, l0);
      split2(v.z, v.w, h1, l1);
      uint32_t addr = sa0 + (uint32_t)(r*256 + ((kc ^ (r & 7)))*16 + half*8);
      sts64(addr,         h0, h1);
      sts64(addr + 16384, l0, l1);
    }
  }

  float oa[16][4];
  #pragma unroll
  for (int i=0;i<16;i++){ oa[i][0]=0.f; oa[i][1]=0.f; oa[i][2]=0.f; oa[i][3]=0.f; }

  int arow = (w & 3)*16 + r7 + ((lane >> 3) & 1)*8;
  int klocal = r7 + ((lane >> 3) & 1)*8;
  int ncsel  = (lane >> 4) & 1;
  int nbase  = (w >> 2) * 16;

  // stage-store indices (per-thread, fixed)
  // ---- prologue: W stage 0 -> buffer 0 ----
  {
    #pragma unroll
    for (int it=0; it<4; it++){
      int idx = tid + it*256;
      int kk = idx >> 6, nc4 = idx & 63;
      float4 v = *(const float4*)(W2 + (kk)*CI + nc4*4);
      int nc = nc4 >> 1, half = nc4 & 1;
      uint32_t h0, l0, h1, l1;
      split2(v.x, v.y, h0, l0);
      split2(v.z, v.w, h1, l1);
      uint32_t addr = sw0 + (uint32_t)(kk*512 + (nc ^ (kk & 7))*16 + half*8);
      sts64(addr,        h0, h1);
      sts64(addr + 8192, l0, l1);
    }
  }

  for (int ks=0; ks<8; ks++){
    float4 wreg[4];
    if (ks < 7){
      #pragma unroll
      for (int it=0; it<4; it++){
        int idx = tid + it*256;
        int kk = idx >> 6, nc4 = idx & 63;
        wreg[it] = *(const float4*)(W2 + ((ks+1)*16 + kk)*CI + nc4*4);
      }
    }
    __syncthreads();     // stage ks (and A tile at ks=0) visible; old reads done
    if (ks < 7){
      uint32_t bo = (uint32_t)(((ks+1) & 1)*16384);
      #pragma unroll
      for (int it=0; it<4; it++){
        int idx = tid + it*256;
        int kk = idx >> 6, nc4 = idx & 63;
        int nc = nc4 >> 1, half = nc4 & 1;
        uint32_t h0, l0, h1, l1;
        split2(wreg[it].x, wreg[it].y, h0, l0);
        split2(wreg[it].z, wreg[it].w, h1, l1);
        uint32_t addr = sw0 + bo + (uint32_t)(kk*512 + (nc ^ (kk & 7))*16 + half*8);
        sts64(addr,        h0, h1);
        sts64(addr + 8192, l0, l1);
      }
    }

    uint32_t cu = (uint32_t)((ks & 1)*16384);
    uint32_t ah[4], al[4];
    {
      int kcv = 2*ks + ((lane >> 4) & 1);
      uint32_t aaddr = sa0 + (uint32_t)(arow*256 + ((kcv ^ r7))*16);
      ldsm4(aaddr, ah);
      ldsm4(aaddr + 16384, al);
    }

    #pragma unroll
    for (int p=0; p<8; p++){
      int nc0 = nbase + 2*p;
      uint32_t waddr = sw0 + cu + (uint32_t)(klocal*512 + (((nc0 + ncsel) ^ r7))*16);
      uint32_t wh[4], wl[4];
      ldsm4t(waddr, wh);
      ldsm4t(waddr + 8192, wl);
      mma_bf16(oa[2*p],   ah, wh[0], wh[1]);
      mma_bf16(oa[2*p],   ah, wl[0], wl[1]);
      mma_bf16(oa[2*p],   al, wh[0], wh[1]);
      mma_bf16(oa[2*p+1], ah, wh[2], wh[3]);
      mma_bf16(oa[2*p+1], ah, wl[2], wl[3]);
      mma_bf16(oa[2*p+1], al, wh[2], wh[3]);
    }
  }

  int p0 = pbase + (w & 3)*16 + gid;
  float* outB = img_out + (size_t)b*CI*HW;
  #pragma unroll
  for (int nc=0; nc<16; nc++){
    int c0 = (w >> 2)*128 + nc*8 + 2*tig;
    float bb0 = __ldg(b2 + c0), bb1 = __ldg(b2 + c0 + 1);
    float v00 = oa[nc][0] + bb0, v01 = oa[nc][1] + bb1;
    float v10 = oa[nc][2] + bb0, v11 = oa[nc][3] + bb1;
    outB[(size_t)c0*HW + p0]           = v00;
    outB[(size_t)(c0+1)*HW + p0]       = v01;
    outB[(size_t)c0*HW + p0 + 8]       = v10;
    outB[(size_t)(c0+1)*HW + p0 + 8]   = v11;
    float e00 = fmaxf(v00, 1e-6f), e01 = fmaxf(v01, 1e-6f);
    float e10 = fmaxf(v10, 1e-6f), e11 = fmaxf(v11, 1e-6f);
    float pc0 = e00*e00*e00 + e10*e10*e10;
    float pc1 = e01*e01*e01 + e11*e11*e11;
    pc0 += __shfl_xor_sync(0xffffffffu, pc0, 4);
    pc1 += __shfl_xor_sync(0xffffffffu, pc1, 4);
    pc0 += __shfl_xor_sync(0xffffffffu, pc0, 8);
    pc1 += __shfl_xor_sync(0xffffffffu, pc1, 8);
    pc0 += __shfl_xor_sync(0xffffffffu, pc0, 16);
    pc1 += __shfl_xor_sync(0xffffffffu, pc1, 16);
    if (lane < 4){
      atomicAdd(&g_imgacc[b*CI + c0],     pc0);
      atomicAdd(&g_imgacc[b*CI + c0 + 1], pc1);
    }
  }
}

// ---------------- K7: cloud l2norm + segmented clamp^3 sum -------------------
__global__ __launch_bounds__(256) void cloud_kernel(const float* __restrict__ cf,
                                                    const int* __restrict__ bids,
                                                    float* __restrict__ cloud_out){
  __shared__ float sseg[NB*DM];
  __shared__ float scnt[NB];
  int tid = threadIdx.x;
  for (int i=tid; i<NB*DM; i+=256) sseg[i] = 0.f;
  if (tid < NB) scnt[tid] = 0.f;
  __syncthreads();
  int w = tid >> 5, lane = tid & 31;
  int rbase = blockIdx.x*64 + w*8;
  #pragma unroll
  for (int i=0;i<8;i++){
    int row = rbase + i;
    int bid = bids[row];
    float4 v = *(const float4*)(cf + row*DM + lane*4);
    float sq = v.x*v.x + v.y*v.y + v.z*v.z + v.w*v.w;
    #pragma unroll
    for (int off=16; off; off>>=1) sq += __shfl_xor_sync(0xffffffffu, sq, off);
    float inv = 1.0f / fmaxf(sqrtf(sq), 1e-12f);
    float x0=v.x*inv, x1=v.y*inv, x2=v.z*inv, x3=v.w*inv;
    *(float4*)(cloud_out + row*DM + lane*4) = make_float4(x0,x1,x2,x3);
    float c0=fmaxf(x0,1e-6f), c1=fmaxf(x1,1e-6f), c2=fmaxf(x2,1e-6f), c3=fmaxf(x3,1e-6f);
    float* sp = sseg + bid*DM + lane*4;
    atomicAdd(sp+0, c0*c0*c0);
    atomicAdd(sp+1, c1*c1*c1);
    atomicAdd(sp+2, c2*c2*c2);
    atomicAdd(sp+3, c3*c3*c3);
    if (lane == 0) atomicAdd(&scnt[bid], 1.0f);
  }
  __syncthreads();
  for (int i=tid; i<NB*DM; i+=256) atomicAdd(&g_seg[i], sseg[i]);
  if (tid < NB) atomicAdd(&g_cnt[tid], scnt[tid]);
}

// ---------------- K8: finalize GeM outputs ----------------
__global__ void finalize_kernel(float* __restrict__ image_gem, float* __restrict__ cloud_gem){
  int i = blockIdx.x*256 + threadIdx.x;
  if (i < NB*CI) image_gem[i] = cbrtf(g_imgacc[i] * (1.0f/1600.0f));
  if (i < NB*DM) cloud_gem[i] = cbrtf(g_seg[i] / fmaxf(g_cnt[i>>7], 1.0f));
}

// ---------------- launch ----------------
extern "C" void kernel_launch(void* const* d_in, const int* in_sizes, int n_in,
                              void* d_out, int out_size){
  const float* img  = (const float*)d_in[0];
  const float* cf   = (const float*)d_in[1];
  const int*   bids = (const int*)  d_in[2];
  const float* W1   = (const float*)d_in[3];
  const float* b1   = (const float*)d_in[4];
  const float* W2   = (const float*)d_in[5];
  const float* b2   = (const float*)d_in[6];

  float* out       = (float*)d_out;
  float* img_out   = out;                                  // 8*256*1600
  float* cloud_out = out + (size_t)NB*CI*HW;               // 32768*128
  float* image_gem = cloud_out + (size_t)NCLOUD*DM;        // 2048
  float* cloud_gem = image_gem + NB*CI;                    // 1024

  zero_kernel<<<8, 256>>>();
  gemm1_mma_kernel<<<200, 256>>>(img, W1, b1);
  attn_bf16_kernel<<<dim3(13, NHEAD, NB), 256>>>();
  gemm2_mma_kernel<<<200, 256>>>(W2, b2, img_out);
  cloud_kernel<<<512, 256>>>(cf, bids, cloud_out);
  finalize_kernel<<<8, 256>>>(image_gem, cloud_gem);
}

// round 15
// speedup vs baseline: 1.0256x; 1.0034x over previous
#include <cuda_runtime.h>
#include <cuda_bf16.h>
#include <cstdint>

// ---------------- constants ----------------
#define NB      8
#define CI      256
#define HW      1600
#define DM      128
#define NHEAD   8
#define DH      16
#define NROWS   (NB*HW)        // 12800
#define NCLOUD  32768

// ---------------- device scratch ----------------
__device__ float g_tok [NROWS*DM];     // l2-normalized image tokens
__device__ float g_attn[NROWS*DM];     // attention output
__device__ float g_m0  [NB*DM];        // per (b, dim) sum of normalized tokens
__device__ float g_imgacc[NB*CI];
__device__ float g_seg  [NB*DM];
__device__ float g_cnt  [NB];

typedef unsigned long long u64;

// ---------------- packed f32x2 helpers ----------------
__device__ __forceinline__ u64 fma2(u64 a, u64 b, u64 c){
  u64 d; asm("fma.rn.f32x2 %0, %1, %2, %3;" : "=l"(d) : "l"(a), "l"(b), "l"(c)); return d;
}
__device__ __forceinline__ u64 mul2(u64 a, u64 b){
  u64 d; asm("mul.rn.f32x2 %0, %1, %2;" : "=l"(d) : "l"(a), "l"(b)); return d;
}
__device__ __forceinline__ u64 add2(u64 a, u64 b){
  u64 d; asm("add.rn.f32x2 %0, %1, %2;" : "=l"(d) : "l"(a), "l"(b)); return d;
}
__device__ __forceinline__ u64 pack2(float x, float y){
  u64 d; asm("mov.b64 %0, {%1, %2};" : "=l"(d) : "f"(x), "f"(y)); return d;
}
__device__ __forceinline__ float2 unpack2(u64 u){
  float2 f; asm("mov.b64 {%0, %1}, %2;" : "=f"(f.x), "=f"(f.y) : "l"(u)); return f;
}

__device__ __forceinline__ uint32_t cvt_bf16x2(u64 p){
  float2 f = unpack2(p);
  uint32_t r;
  asm("cvt.rn.bf16x2.f32 %0, %1, %2;" : "=r"(r) : "f"(f.y), "f"(f.x));
  return r;
}
__device__ __forceinline__ uint32_t cvt_bf16x2_ff(float lo, float hi){
  uint32_t r;
  asm("cvt.rn.bf16x2.f32 %0, %1, %2;" : "=r"(r) : "f"(hi), "f"(lo));
  return r;
}
__device__ __forceinline__ uint32_t packbf(__nv_bfloat16 a, __nv_bfloat16 b){
  __nv_bfloat162 t(a, b);
  return *reinterpret_cast<uint32_t*>(&t);
}

// ---------------- mma / ldmatrix helpers ----------------
__device__ __forceinline__ void mma_bf16(float* c, const uint32_t* a, uint32_t b0, uint32_t b1){
  asm volatile("mma.sync.aligned.m16n8k16.row.col.f32.bf16.bf16.f32 "
      "{%0,%1,%2,%3}, {%4,%5,%6,%7}, {%8,%9}, {%0,%1,%2,%3};"
      : "+f"(c[0]), "+f"(c[1]), "+f"(c[2]), "+f"(c[3])
      : "r"(a[0]), "r"(a[1]), "r"(a[2]), "r"(a[3]), "r"(b0), "r"(b1));
}
__device__ __forceinline__ void ldsm4(uint32_t addr, uint32_t* r){
  asm volatile("ldmatrix.sync.aligned.m8n8.x4.shared.b16 {%0,%1,%2,%3}, [%4];"
      : "=r"(r[0]), "=r"(r[1]), "=r"(r[2]), "=r"(r[3]) : "r"(addr));
}
__device__ __forceinline__ void ldsm4t(uint32_t addr, uint32_t* r){
  asm volatile("ldmatrix.sync.aligned.m8n8.x4.trans.shared.b16 {%0,%1,%2,%3}, [%4];"
      : "=r"(r[0]), "=r"(r[1]), "=r"(r[2]), "=r"(r[3]) : "r"(addr));
}
__device__ __forceinline__ void sts64(uint32_t addr, uint32_t r0, uint32_t r1){
  asm volatile("st.shared.v2.b32 [%0], {%1,%2};" :: "r"(addr), "r"(r0), "r"(r1));
}

// split pair of floats to hi/lo bf16x2
__device__ __forceinline__ void split2(float x0, float x1, uint32_t& hi, uint32_t& lo){
  __nv_bfloat16 h0 = __float2bfloat16_rn(x0);
  __nv_bfloat16 h1 = __float2bfloat16_rn(x1);
  float r0 = x0 - __bfloat162float(h0);
  float r1 = x1 - __bfloat162float(h1);
  hi = packbf(h0, h1);
  lo = packbf(__float2bfloat16_rn(r0), __float2bfloat16_rn(r1));
}

// ---------------- K0: zero accumulators ----------------
__global__ void zero_kernel(){
  int i = blockIdx.x*256 + threadIdx.x;
  if (i < NB*CI) g_imgacc[i] = 0.f;
  if (i < NB*DM){ g_seg[i] = 0.f; g_m0[i] = 0.f; }
  if (i < NB)    g_cnt[i]  = 0.f;
}

// ---------------- K1: gemm1 split-bf16 mma, double-buffered stages -----------
__global__ __launch_bounds__(256, 2) void gemm1_mma_kernel(const float* __restrict__ img,
                                                           const float* __restrict__ W1,
                                                           const float* __restrict__ b1){
  __shared__ __align__(128) unsigned char sAh[2][2048];
  __shared__ __align__(128) unsigned char sAl[2][2048];
  __shared__ __align__(128) unsigned char sWh[2][4096];
  __shared__ __align__(128) unsigned char sWl[2][4096];
  __shared__ __align__(16)  float sOut[64*132];
  int tile = blockIdx.x;
  int b = tile / 25, pbase = (tile % 25) * 64;
  int tid = threadIdx.x, w = tid >> 5, lane = tid & 31;
  int gid = lane >> 2, tig = lane & 3, r7 = lane & 7;

  uint32_t ah0 = (uint32_t)__cvta_generic_to_shared(&sAh[0][0]);
  uint32_t al0 = (uint32_t)__cvta_generic_to_shared(&sAl[0][0]);
  uint32_t wh0 = (uint32_t)__cvta_generic_to_shared(&sWh[0][0]);
  uint32_t wl0 = (uint32_t)__cvta_generic_to_shared(&sWl[0][0]);

  const float* Abase = img + b*CI*HW + pbase;

  float oa[8][4];
  #pragma unroll
  for (int i=0;i<8;i++){ oa[i][0]=0.f; oa[i][1]=0.f; oa[i][2]=0.f; oa[i][3]=0.f; }

  int kkA = r7 + ((lane >> 4) & 1)*8;
  int uA  = (w & 3)*2 + ((lane >> 3) & 1);
  uint32_t aoff = (uint32_t)(kkA*128 + ((uA ^ (kkA & 7)))*16);
  int kkW = r7 + ((lane >> 3) & 1)*8;
  int nsel = (lane >> 4) & 1;
  int nbase8 = (w >> 2)*8;

  int kkSa = tid >> 4, r4 = tid & 15;
  int kkSw = tid >> 5, c4 = tid & 31;
  int ncw = c4 >> 1, halfw = c4 & 1;
  uint32_t aSaddr  = (uint32_t)(kkSa*128 + (((r4 >> 1) ^ (kkSa & 7)))*16 + (r4 & 1)*8);
  uint32_t wSaddr0 = (uint32_t)(kkSw*256 + ((ncw ^ (kkSw & 7)))*16 + halfw*8);
  uint32_t wSaddr1 = (uint32_t)((kkSw+8)*256 + ((ncw ^ ((kkSw+8) & 7)))*16 + halfw*8);

  {
    float4 va  = *(const float4*)(Abase + (kkSa)*HW + r4*4);
    float4 vw0 = *(const float4*)(W1 + (kkSw)*DM + c4*4);
    float4 vw1 = *(const float4*)(W1 + (8 + kkSw)*DM + c4*4);
    uint32_t h0,l0,h1,l1;
    split2(va.x, va.y, h0, l0); split2(va.z, va.w, h1, l1);
    sts64(ah0 + aSaddr, h0, h1);
    sts64(al0 + aSaddr, l0, l1);
    split2(vw0.x, vw0.y, h0, l0); split2(vw0.z, vw0.w, h1, l1);
    sts64(wh0 + wSaddr0, h0, h1);
    sts64(wl0 + wSaddr0, l0, l1);
    split2(vw1.x, vw1.y, h0, l0); split2(vw1.z, vw1.w, h1, l1);
    sts64(wh0 + wSaddr1, h0, h1);
    sts64(wl0 + wSaddr1, l0, l1);
  }

  for (int ks=0; ks<16; ks++){
    float4 va, vw0, vw1;
    if (ks < 15){
      va  = *(const float4*)(Abase + ((ks+1)*16 + kkSa)*HW + r4*4);
      vw0 = *(const float4*)(W1 + ((ks+1)*16 + kkSw)*DM + c4*4);
      vw1 = *(const float4*)(W1 + ((ks+1)*16 + 8 + kkSw)*DM + c4*4);
    }
    __syncthreads();
    if (ks < 15){
      uint32_t bo = (uint32_t)(((ks+1) & 1));
      uint32_t h0,l0,h1,l1;
      split2(va.x, va.y, h0, l0); split2(va.z, va.w, h1, l1);
      sts64(ah0 + bo*2048 + aSaddr, h0, h1);
      sts64(al0 + bo*2048 + aSaddr, l0, l1);
      split2(vw0.x, vw0.y, h0, l0); split2(vw0.z, vw0.w, h1, l1);
      sts64(wh0 + bo*4096 + wSaddr0, h0, h1);
      sts64(wl0 + bo*4096 + wSaddr0, l0, l1);
      split2(vw1.x, vw1.y, h0, l0); split2(vw1.z, vw1.w, h1, l1);
      sts64(wh0 + bo*4096 + wSaddr1, h0, h1);
      sts64(wl0 + bo*4096 + wSaddr1, l0, l1);
    }

    uint32_t cu = (uint32_t)(ks & 1);
    uint32_t ah[4], al[4];
    ldsm4t(ah0 + cu*2048 + aoff, ah);
    ldsm4t(al0 + cu*2048 + aoff, al);

    #pragma unroll
    for (int p=0; p<4; p++){
      int unit = nbase8 + 2*p + nsel;
      uint32_t waddr = cu*4096 + (uint32_t)(kkW*256 + ((unit ^ (kkW & 7)))*16);
      uint32_t wh[4], wl[4];
      ldsm4t(wh0 + waddr, wh);
      ldsm4t(wl0 + waddr, wl);
      mma_bf16(oa[2*p],   ah, wh[0], wh[1]);
      mma_bf16(oa[2*p],   ah, wl[0], wl[1]);
      mma_bf16(oa[2*p],   al, wh[0], wh[1]);
      mma_bf16(oa[2*p+1], ah, wh[2], wh[3]);
      mma_bf16(oa[2*p+1], ah, wl[2], wl[3]);
      mma_bf16(oa[2*p+1], al, wh[2], wh[3]);
    }
  }
  __syncthreads();

  {
    int r0 = (w & 3)*16 + gid;
    #pragma unroll
    for (int p=0; p<8; p++){
      int c0 = (w >> 2)*64 + p*8 + 2*tig;
      sOut[r0*132 + c0]       = oa[p][0];
      sOut[r0*132 + c0 + 1]   = oa[p][1];
      sOut[(r0+8)*132 + c0]   = oa[p][2];
      sOut[(r0+8)*132 + c0+1] = oa[p][3];
    }
  }
  __syncthreads();

  {
    int r = tid >> 2, seg = tid & 3;
    float xv[32];
    float s = 0.f;
    float* op = sOut + r*132 + seg*32;
    const float* bp = b1 + seg*32;
    #pragma unroll
    for (int j4=0; j4<8; j4++){
      float4 xb = *(float4*)(op + j4*4);
      float4 bb = *(const float4*)(bp + j4*4);
      float x0 = xb.x + bb.x, x1 = xb.y + bb.y, x2 = xb.z + bb.z, x3 = xb.w + bb.w;
      xv[4*j4]=x0; xv[4*j4+1]=x1; xv[4*j4+2]=x2; xv[4*j4+3]=x3;
      s += x0*x0 + x1*x1 + x2*x2 + x3*x3;
    }
    s += __shfl_xor_sync(0xffffffffu, s, 1);
    s += __shfl_xor_sync(0xffffffffu, s, 2);
    float inv = 1.0f / fmaxf(sqrtf(s), 1e-12f);
    float* tp = g_tok + (size_t)(tile*64 + r)*DM + seg*32;
    #pragma unroll
    for (int j4=0; j4<8; j4++){
      float4 o = make_float4(xv[4*j4]*inv, xv[4*j4+1]*inv, xv[4*j4+2]*inv, xv[4*j4+3]*inv);
      *(float4*)(tp + j4*4) = o;
      *(float4*)(op + j4*4) = o;
    }
  }
  __syncthreads();

  if (tid < 128){
    float cs = 0.f;
    #pragma unroll 8
    for (int r=0; r<64; r++) cs += sOut[r*132 + tid];
    atomicAdd(&g_m0[b*DM + tid], cs);
  }
}

// ---------------- K3: attention, 128-key tiles (13 syncs), deg-3 expm1 -------
__global__ __launch_bounds__(256) void attn_bf16_kernel(){
  __shared__ __align__(1024) unsigned char sbuf[2][4096];
  int b = blockIdx.z, h = blockIdx.y;
  int tid = threadIdx.x, w = tid >> 5, lane = tid & 31;
  int gid = lane >> 2, tig = lane & 3, r7 = lane & 7;
  const float* base = g_tok + b*HW*DM + h*DH;
  int qb0 = blockIdx.x*128 + w*16;
  bool wstore = (qb0 < HW);
  int qbase = wstore ? qb0 : (HW - 16);

  uint32_t qh[4];
  #pragma unroll
  for (int i=0;i<4;i++){
    int row = qbase + gid + (i & 1)*8;
    int col = 2*tig + (i >> 1)*8;
    float2 v = *(const float2*)(base + row*DM + col);
    qh[i] = packbf(__float2bfloat16_rn(v.x*0.25f), __float2bfloat16_rn(v.y*0.25f));
  }

  float oa0E[4] = {0.f,0.f,0.f,0.f};
  float oa1E[4] = {0.f,0.f,0.f,0.f};
  float oa0O[4] = {0.f,0.f,0.f,0.f};
  float oa1O[4] = {0.f,0.f,0.f,0.f};
  u64 lA01 = 0ULL, lA23 = 0ULL, lB01 = 0ULL, lB23 = 0ULL;

  const u64 C6  = pack2(1.6666667e-1f, 1.6666667e-1f);
  const u64 CH  = pack2(0.5f, 0.5f);
  const u64 C1  = pack2(1.0f, 1.0f);

  uint32_t sb0 = (uint32_t)__cvta_generic_to_shared(&sbuf[0][0]);
  // planes now 2048B apart (128 keys x 16B)
  uint32_t aScore = sb0 + (uint32_t)((r7 + ((lane >> 4) & 1)*8)*16 + ((lane >> 3) & 1)*2048);
  uint32_t aPV    = sb0 + (uint32_t)((r7 + ((lane >> 3) & 1)*8)*16 + ((lane >> 4) & 1)*2048);

  // tile stores: 2 float4/thread; key1 = key0 + 64 (same quarter)
  int key0 = tid >> 2, quarter = tid & 3;
  const float* g0 = base + key0*DM + quarter*4;
  const float* g1 = g0 + 64*DM;
  uint32_t dst0 = sb0 + (uint32_t)((quarter >> 1)*2048 + key0*16 + (quarter & 1)*8);
  uint32_t dst1 = dst0 + 64*16;

  // prologue: tile 0 (keys 0..127 all valid)
  {
    float4 v0 = *(const float4*)(g0);
    float4 v1 = *(const float4*)(g1);
    sts64(dst0, cvt_bf16x2_ff(v0.x, v0.y), cvt_bf16x2_ff(v0.z, v0.w));
    sts64(dst1, cvt_bf16x2_ff(v1.x, v1.y), cvt_bf16x2_ff(v1.z, v1.w));
  }
  __syncthreads();

  for (int kb=0; kb<13; kb++){
    float4 nv0, nv1;
    if (kb < 12){
      nv0 = *(const float4*)(g0 + (kb+1)*128*DM);           // key0 <= 63: always valid
      int gk1 = (kb+1)*128 + key0 + 64;
      if (gk1 < HW) nv1 = *(const float4*)(g1 + (kb+1)*128*DM);
      else          nv1 = make_float4(0.f, 0.f, 0.f, 0.f);  // zero keys are exp-neutral
    }
    uint32_t bufoff = (uint32_t)((kb & 1)*4096);
    uint32_t aS = aScore + bufoff;
    uint32_t aP = aPV + bufoff;

    #pragma unroll
    for (int ck=0; ck<8; ck++){
      uint32_t off = (uint32_t)(ck*256);
      uint32_t kh[4], vv[4];
      ldsm4 (aS + off, kh);
      ldsm4t(aP + off, vv);

      float cA[4] = {0.f,0.f,0.f,0.f};
      float cB[4] = {0.f,0.f,0.f,0.f};
      mma_bf16(cA, qh, kh[0], kh[1]);
      mma_bf16(cB, qh, kh[2], kh[3]);

      u64 tA01 = pack2(cA[0], cA[1]);
      u64 tA23 = pack2(cA[2], cA[3]);
      u64 tB01 = pack2(cB[0], cB[1]);
      u64 tB23 = pack2(cB[2], cB[3]);
      u64 wA01 = fma2(tA01, C6, CH);
      u64 wA23 = fma2(tA23, C6, CH);
      u64 wB01 = fma2(tB01, C6, CH);
      u64 wB23 = fma2(tB23, C6, CH);
      wA01 = fma2(tA01, wA01, C1);  wA23 = fma2(tA23, wA23, C1);
      wB01 = fma2(tB01, wB01, C1);  wB23 = fma2(tB23, wB23, C1);
      u64 uA01 = mul2(tA01, wA01);
      u64 uA23 = mul2(tA23, wA23);
      u64 uB01 = mul2(tB01, wB01);
      u64 uB23 = mul2(tB23, wB23);
      lA01 = add2(lA01, uA01);
      lA23 = add2(lA23, uA23);
      lB01 = add2(lB01, uB01);
      lB23 = add2(lB23, uB23);

      uint32_t pa[4];
      pa[0] = cvt_bf16x2(uA01);
      pa[1] = cvt_bf16x2(uA23);
      pa[2] = cvt_bf16x2(uB01);
      pa[3] = cvt_bf16x2(uB23);

      if (ck & 1){
        mma_bf16(oa0O, pa, vv[0], vv[1]);
        mma_bf16(oa1O, pa, vv[2], vv[3]);
      } else {
        mma_bf16(oa0E, pa, vv[0], vv[1]);
        mma_bf16(oa1E, pa, vv[2], vv[3]);
      }
    }

    if (kb < 12){
      uint32_t d = (uint32_t)(((kb+1) & 1)*4096);
      sts64(dst0 + d, cvt_bf16x2_ff(nv0.x, nv0.y), cvt_bf16x2_ff(nv0.z, nv0.w));
      sts64(dst1 + d, cvt_bf16x2_ff(nv1.x, nv1.y), cvt_bf16x2_ff(nv1.z, nv1.w));
    }
    __syncthreads();
  }

  float oa0[4], oa1[4];
  #pragma unroll
  for (int i=0;i<4;i++){ oa0[i] = oa0E[i] + oa0O[i]; oa1[i] = oa1E[i] + oa1O[i]; }
  float2 fA01 = unpack2(lA01), fA23 = unpack2(lA23);
  float2 fB01 = unpack2(lB01), fB23 = unpack2(lB23);
  float lr0 = fA01.x + fA01.y + fB01.x + fB01.y;
  float lr8 = fA23.x + fA23.y + fB23.x + fB23.y;
  lr0 += __shfl_xor_sync(0xffffffffu, lr0, 1);
  lr0 += __shfl_xor_sync(0xffffffffu, lr0, 2);
  lr8 += __shfl_xor_sync(0xffffffffu, lr8, 1);
  lr8 += __shfl_xor_sync(0xffffffffu, lr8, 2);
  float inv0 = 1.0f / (1600.0f + lr0);
  float inv8 = 1.0f / (1600.0f + lr8);

  if (wstore){
    const float* m0p = g_m0 + b*DM + h*DH;
    float* outb = g_attn + (b*HW + qbase)*DM + h*DH;
    float* oas[2] = {oa0, oa1};
    #pragma unroll
    for (int nt=0; nt<2; nt++){
      int d0 = nt*8 + 2*tig;
      float m0a = m0p[d0], m0b = m0p[d0+1];
      outb[(gid  )*DM + d0    ] = (oas[nt][0] + m0a) * inv0;
      outb[(gid  )*DM + d0 + 1] = (oas[nt][1] + m0b) * inv0;
      outb[(gid+8)*DM + d0    ] = (oas[nt][2] + m0a) * inv8;
      outb[(gid+8)*DM + d0 + 1] = (oas[nt][3] + m0b) * inv8;
    }
  }
}

// ---------------- K4: gemm2 split-bf16 mma, 32-row tiles, 3 CTAs/SM ----------
// 32 rows x 256 cols per CTA, grid 400. Warp: m-sub (w&1)*16, n-group (w>>1)*64.
__global__ __launch_bounds__(256, 3) void gemm2_mma_kernel(const float* __restrict__ W2,
                                                           const float* __restrict__ b2,
                                                           float* __restrict__ img_out){
  __shared__ __align__(1024) unsigned char sA[2][8192];   // hi/lo A planes (32r x 128k)
  __shared__ __align__(1024) unsigned char sW[2][8192];   // hi/lo W stage (16k x 256n)
  int tile = blockIdx.x;
  int b = tile / 50, pbase = (tile % 50) * 32;
  int tid = threadIdx.x, w = tid >> 5, lane = tid & 31;
  int gid = lane >> 2, tig = lane & 3, r7 = lane & 7;

  uint32_t sa0 = (uint32_t)__cvta_generic_to_shared(&sA[0][0]);
  uint32_t sw0 = (uint32_t)__cvta_generic_to_shared(&sW[0][0]);

  // ---- A tile load + split-store ----
  {
    const float* Abase = g_attn + (size_t)(tile*32)*DM;
    #pragma unroll
    for (int it=0; it<4; it++){
      int idx = tid + it*256;
      int r = idx >> 5, kc4 = idx & 31;
      int kc = kc4 >> 1, half = kc4 & 1;
      float4 v = *(const float4*)(Abase + r*DM + kc4*4);
      uint32_t h0, l0, h1, l1;
      split2(v.x, v.y, h0, l0);
      split2(v.z, v.w, h1, l1);
      uint32_t addr = sa0 + (uint32_t)(r*256 + ((kc ^ (r & 7)))*16 + half*8);
      sts64(addr,        h0, h1);
      sts64(addr + 8192, l0, l1);
    }
  }

  float oa[8][4];
  #pragma unroll
  for (int i=0;i<8;i++){ oa[i][0]=0.f; oa[i][1]=0.f; oa[i][2]=0.f; oa[i][3]=0.f; }

  int arow = (w & 1)*16 + r7 + ((lane >> 3) & 1)*8;
  int klocal = r7 + ((lane >> 3) & 1)*8;
  int ncsel  = (lane >> 4) & 1;
  int nbase  = (w >> 1) * 8;            // n-units of 8 cols; warp covers 8 units

  for (int ks=0; ks<8; ks++){
    __syncthreads();    // consumers done with previous stage (and A stored at ks=0)
    #pragma unroll
    for (int it=0; it<4; it++){
      int idx = tid + it*256;
      int kk = idx >> 6, nc4 = idx & 63;
      float4 v = *(const float4*)(W2 + (ks*16 + kk)*CI + nc4*4);
      int nc = nc4 >> 1, half = nc4 & 1;
      uint32_t h0, l0, h1, l1;
      split2(v.x, v.y, h0, l0);
      split2(v.z, v.w, h1, l1);
      uint32_t addr = sw0 + (uint32_t)(kk*512 + (nc ^ (kk & 7))*16 + half*8);
      sts64(addr,        h0, h1);
      sts64(addr + 8192, l0, l1);
    }
    __syncthreads();

    uint32_t ah[4], al[4];
    {
      int kcv = 2*ks + ((lane >> 4) & 1);
      uint32_t aaddr = sa0 + (uint32_t)(arow*256 + ((kcv ^ r7))*16);
      ldsm4(aaddr, ah);
      ldsm4(aaddr + 8192, al);
    }

    #pragma unroll
    for (int p=0; p<4; p++){
      int nc0 = nbase + 2*p;
      uint32_t waddr = sw0 + (uint32_t)(klocal*512 + (((nc0 + ncsel) ^ r7))*16);
      uint32_t wh[4], wl[4];
      ldsm4t(waddr, wh);
      ldsm4t(waddr + 8192, wl);
      mma_bf16(oa[2*p],   ah, wh[0], wh[1]);
      mma_bf16(oa[2*p],   ah, wl[0], wl[1]);
      mma_bf16(oa[2*p],   al, wh[0], wh[1]);
      mma_bf16(oa[2*p+1], ah, wh[2], wh[3]);
      mma_bf16(oa[2*p+1], ah, wl[2], wl[3]);
      mma_bf16(oa[2*p+1], al, wh[2], wh[3]);
    }
  }

  int p0 = pbase + (w & 1)*16 + gid;
  float* outB = img_out + (size_t)b*CI*HW;
  #pragma unroll
  for (int nc=0; nc<8; nc++){
    int c0 = (w >> 1)*64 + nc*8 + 2*tig;
    float bb0 = __ldg(b2 + c0), bb1 = __ldg(b2 + c0 + 1);
    float v00 = oa[nc][0] + bb0, v01 = oa[nc][1] + bb1;
    float v10 = oa[nc][2] + bb0, v11 = oa[nc][3] + bb1;
    outB[(size_t)c0*HW + p0]           = v00;
    outB[(size_t)(c0+1)*HW + p0]       = v01;
    outB[(size_t)c0*HW + p0 + 8]       = v10;
    outB[(size_t)(c0+1)*HW + p0 + 8]   = v11;
    float e00 = fmaxf(v00, 1e-6f), e01 = fmaxf(v01, 1e-6f);
    float e10 = fmaxf(v10, 1e-6f), e11 = fmaxf(v11, 1e-6f);
    float pc0 = e00*e00*e00 + e10*e10*e10;
    float pc1 = e01*e01*e01 + e11*e11*e11;
    pc0 += __shfl_xor_sync(0xffffffffu, pc0, 4);
    pc1 += __shfl_xor_sync(0xffffffffu, pc1, 4);
    pc0 += __shfl_xor_sync(0xffffffffu, pc0, 8);
    pc1 += __shfl_xor_sync(0xffffffffu, pc1, 8);
    pc0 += __shfl_xor_sync(0xffffffffu, pc0, 16);
    pc1 += __shfl_xor_sync(0xffffffffu, pc1, 16);
    if (lane < 4){
      atomicAdd(&g_imgacc[b*CI + c0],     pc0);
      atomicAdd(&g_imgacc[b*CI + c0 + 1], pc1);
    }
  }
}

// ---------------- K7: cloud l2norm + segmented clamp^3 sum -------------------
__global__ __launch_bounds__(256) void cloud_kernel(const float* __restrict__ cf,
                                                    const int* __restrict__ bids,
                                                    float* __restrict__ cloud_out){
  __shared__ float sseg[NB*DM];
  __shared__ float scnt[NB];
  int tid = threadIdx.x;
  for (int i=tid; i<NB*DM; i+=256) sseg[i] = 0.f;
  if (tid < NB) scnt[tid] = 0.f;
  __syncthreads();
  int w = tid >> 5, lane = tid & 31;
  int rbase = blockIdx.x*64 + w*8;
  #pragma unroll
  for (int i=0;i<8;i++){
    int row = rbase + i;
    int bid = bids[row];
    float4 v = *(const float4*)(cf + row*DM + lane*4);
    float sq = v.x*v.x + v.y*v.y + v.z*v.z + v.w*v.w;
    #pragma unroll
    for (int off=16; off; off>>=1) sq += __shfl_xor_sync(0xffffffffu, sq, off);
    float inv = 1.0f / fmaxf(sqrtf(sq), 1e-12f);
    float x0=v.x*inv, x1=v.y*inv, x2=v.z*inv, x3=v.w*inv;
    *(float4*)(cloud_out + row*DM + lane*4) = make_float4(x0,x1,x2,x3);
    float c0=fmaxf(x0,1e-6f), c1=fmaxf(x1,1e-6f), c2=fmaxf(x2,1e-6f), c3=fmaxf(x3,1e-6f);
    float* sp = sseg + bid*DM + lane*4;
    atomicAdd(sp+0, c0*c0*c0);
    atomicAdd(sp+1, c1*c1*c1);
    atomicAdd(sp+2, c2*c2*c2);
    atomicAdd(sp+3, c3*c3*c3);
    if (lane == 0) atomicAdd(&scnt[bid], 1.0f);
  }
  __syncthreads();
  for (int i=tid; i<NB*DM; i+=256) atomicAdd(&g_seg[i], sseg[i]);
  if (tid < NB) atomicAdd(&g_cnt[tid], scnt[tid]);
}

// ---------------- K8: finalize GeM outputs ----------------
__global__ void finalize_kernel(float* __restrict__ image_gem, float* __restrict__ cloud_gem){
  int i = blockIdx.x*256 + threadIdx.x;
  if (i < NB*CI) image_gem[i] = cbrtf(g_imgacc[i] * (1.0f/1600.0f));
  if (i < NB*DM) cloud_gem[i] = cbrtf(g_seg[i] / fmaxf(g_cnt[i>>7], 1.0f));
}

// ---------------- launch ----------------
extern "C" void kernel_launch(void* const* d_in, const int* in_sizes, int n_in,
                              void* d_out, int out_size){
  const float* img  = (const float*)d_in[0];
  const float* cf   = (const float*)d_in[1];
  const int*   bids = (const int*)  d_in[2];
  const float* W1   = (const float*)d_in[3];
  const float* b1   = (const float*)d_in[4];
  const float* W2   = (const float*)d_in[5];
  const float* b2   = (const float*)d_in[6];

  float* out       = (float*)d_out;
  float* img_out   = out;                                  // 8*256*1600
  float* cloud_out = out + (size_t)NB*CI*HW;               // 32768*128
  float* image_gem = cloud_out + (size_t)NCLOUD*DM;        // 2048
  float* cloud_gem = image_gem + NB*CI;                    // 1024

  zero_kernel<<<8, 256>>>();
  gemm1_mma_kernel<<<200, 256>>>(img, W1, b1);
  attn_bf16_kernel<<<dim3(13, NHEAD, NB), 256>>>();
  gemm2_mma_kernel<<<400, 256>>>(W2, b2, img_out);
  cloud_kernel<<<512, 256>>>(cf, bids, cloud_out);
  finalize_kernel<<<8, 256>>>(image_gem, cloud_gem);
}

// round 16
// speedup vs baseline: 1.0648x; 1.0382x over previous
#include <cuda_runtime.h>
#include <cuda_bf16.h>
#include <cstdint>

// ---------------- constants ----------------
#define NB      8
#define CI      256
#define HW      1600
#define DM      128
#define NHEAD   8
#define DH      16
#define NROWS   (NB*HW)        // 12800
#define NCLOUD  32768

// ---------------- device scratch ----------------
__device__ float g_tok [NROWS*DM];     // l2-normalized image tokens
__device__ float g_attn[NROWS*DM];     // attention output
__device__ float g_m0  [NB*DM];        // per (b, dim) sum of normalized tokens
__device__ float g_imgacc[NB*CI];
__device__ float g_seg  [NB*DM];
__device__ float g_cnt  [NB];

typedef unsigned long long u64;

// ---------------- packed f32x2 helpers ----------------
__device__ __forceinline__ u64 fma2(u64 a, u64 b, u64 c){
  u64 d; asm("fma.rn.f32x2 %0, %1, %2, %3;" : "=l"(d) : "l"(a), "l"(b), "l"(c)); return d;
}
__device__ __forceinline__ u64 mul2(u64 a, u64 b){
  u64 d; asm("mul.rn.f32x2 %0, %1, %2;" : "=l"(d) : "l"(a), "l"(b)); return d;
}
__device__ __forceinline__ u64 pack2(float x, float y){
  u64 d; asm("mov.b64 %0, {%1, %2};" : "=l"(d) : "f"(x), "f"(y)); return d;
}
__device__ __forceinline__ float2 unpack2(u64 u){
  float2 f; asm("mov.b64 {%0, %1}, %2;" : "=f"(f.x), "=f"(f.y) : "l"(u)); return f;
}

__device__ __forceinline__ uint32_t cvt_bf16x2(u64 p){
  float2 f = unpack2(p);
  uint32_t r;
  asm("cvt.rn.bf16x2.f32 %0, %1, %2;" : "=r"(r) : "f"(f.y), "f"(f.x));
  return r;
}
__device__ __forceinline__ uint32_t cvt_bf16x2_ff(float lo, float hi){
  uint32_t r;
  asm("cvt.rn.bf16x2.f32 %0, %1, %2;" : "=r"(r) : "f"(hi), "f"(lo));
  return r;
}
__device__ __forceinline__ uint32_t packbf(__nv_bfloat16 a, __nv_bfloat16 b){
  __nv_bfloat162 t(a, b);
  return *reinterpret_cast<uint32_t*>(&t);
}

// ---------------- mma / ldmatrix helpers ----------------
__device__ __forceinline__ void mma_bf16(float* c, const uint32_t* a, uint32_t b0, uint32_t b1){
  asm volatile("mma.sync.aligned.m16n8k16.row.col.f32.bf16.bf16.f32 "
      "{%0,%1,%2,%3}, {%4,%5,%6,%7}, {%8,%9}, {%0,%1,%2,%3};"
      : "+f"(c[0]), "+f"(c[1]), "+f"(c[2]), "+f"(c[3])
      : "r"(a[0]), "r"(a[1]), "r"(a[2]), "r"(a[3]), "r"(b0), "r"(b1));
}
__device__ __forceinline__ void ldsm4(uint32_t addr, uint32_t* r){
  asm volatile("ldmatrix.sync.aligned.m8n8.x4.shared.b16 {%0,%1,%2,%3}, [%4];"
      : "=r"(r[0]), "=r"(r[1]), "=r"(r[2]), "=r"(r[3]) : "r"(addr));
}
__device__ __forceinline__ void ldsm4t(uint32_t addr, uint32_t* r){
  asm volatile("ldmatrix.sync.aligned.m8n8.x4.trans.shared.b16 {%0,%1,%2,%3}, [%4];"
      : "=r"(r[0]), "=r"(r[1]), "=r"(r[2]), "=r"(r[3]) : "r"(addr));
}
__device__ __forceinline__ void sts64(uint32_t addr, uint32_t r0, uint32_t r1){
  asm volatile("st.shared.v2.b32 [%0], {%1,%2};" :: "r"(addr), "r"(r0), "r"(r1));
}

// split pair of floats to hi/lo bf16x2
__device__ __forceinline__ void split2(float x0, float x1, uint32_t& hi, uint32_t& lo){
  __nv_bfloat16 h0 = __float2bfloat16_rn(x0);
  __nv_bfloat16 h1 = __float2bfloat16_rn(x1);
  float r0 = x0 - __bfloat162float(h0);
  float r1 = x1 - __bfloat162float(h1);
  hi = packbf(h0, h1);
  lo = packbf(__float2bfloat16_rn(r0), __float2bfloat16_rn(r1));
}

// ---------------- K0: zero accumulators ----------------
__global__ void zero_kernel(){
  int i = blockIdx.x*256 + threadIdx.x;
  if (i < NB*CI) g_imgacc[i] = 0.f;
  if (i < NB*DM){ g_seg[i] = 0.f; g_m0[i] = 0.f; }
  if (i < NB)    g_cnt[i]  = 0.f;
}

// ---------------- K1: gemm1 split-bf16 mma, double-buffered stages -----------
__global__ __launch_bounds__(256, 2) void gemm1_mma_kernel(const float* __restrict__ img,
                                                           const float* __restrict__ W1,
                                                           const float* __restrict__ b1){
  __shared__ __align__(128) unsigned char sAh[2][2048];
  __shared__ __align__(128) unsigned char sAl[2][2048];
  __shared__ __align__(128) unsigned char sWh[2][4096];
  __shared__ __align__(128) unsigned char sWl[2][4096];
  __shared__ __align__(16)  float sOut[64*132];
  int tile = blockIdx.x;
  int b = tile / 25, pbase = (tile % 25) * 64;
  int tid = threadIdx.x, w = tid >> 5, lane = tid & 31;
  int gid = lane >> 2, tig = lane & 3, r7 = lane & 7;

  uint32_t ah0 = (uint32_t)__cvta_generic_to_shared(&sAh[0][0]);
  uint32_t al0 = (uint32_t)__cvta_generic_to_shared(&sAl[0][0]);
  uint32_t wh0 = (uint32_t)__cvta_generic_to_shared(&sWh[0][0]);
  uint32_t wl0 = (uint32_t)__cvta_generic_to_shared(&sWl[0][0]);

  const float* Abase = img + b*CI*HW + pbase;

  float oa[8][4];
  #pragma unroll
  for (int i=0;i<8;i++){ oa[i][0]=0.f; oa[i][1]=0.f; oa[i][2]=0.f; oa[i][3]=0.f; }

  int kkA = r7 + ((lane >> 4) & 1)*8;
  int uA  = (w & 3)*2 + ((lane >> 3) & 1);
  uint32_t aoff = (uint32_t)(kkA*128 + ((uA ^ (kkA & 7)))*16);
  int kkW = r7 + ((lane >> 3) & 1)*8;
  int nsel = (lane >> 4) & 1;
  int nbase8 = (w >> 2)*8;

  int kkSa = tid >> 4, r4 = tid & 15;
  int kkSw = tid >> 5, c4 = tid & 31;
  int ncw = c4 >> 1, halfw = c4 & 1;
  uint32_t aSaddr  = (uint32_t)(kkSa*128 + (((r4 >> 1) ^ (kkSa & 7)))*16 + (r4 & 1)*8);
  uint32_t wSaddr0 = (uint32_t)(kkSw*256 + ((ncw ^ (kkSw & 7)))*16 + halfw*8);
  uint32_t wSaddr1 = (uint32_t)((kkSw+8)*256 + ((ncw ^ ((kkSw+8) & 7)))*16 + halfw*8);

  {
    float4 va  = *(const float4*)(Abase + (kkSa)*HW + r4*4);
    float4 vw0 = *(const float4*)(W1 + (kkSw)*DM + c4*4);
    float4 vw1 = *(const float4*)(W1 + (8 + kkSw)*DM + c4*4);
    uint32_t h0,l0,h1,l1;
    split2(va.x, va.y, h0, l0); split2(va.z, va.w, h1, l1);
    sts64(ah0 + aSaddr, h0, h1);
    sts64(al0 + aSaddr, l0, l1);
    split2(vw0.x, vw0.y, h0, l0); split2(vw0.z, vw0.w, h1, l1);
    sts64(wh0 + wSaddr0, h0, h1);
    sts64(wl0 + wSaddr0, l0, l1);
    split2(vw1.x, vw1.y, h0, l0); split2(vw1.z, vw1.w, h1, l1);
    sts64(wh0 + wSaddr1, h0, h1);
    sts64(wl0 + wSaddr1, l0, l1);
  }

  for (int ks=0; ks<16; ks++){
    float4 va, vw0, vw1;
    if (ks < 15){
      va  = *(const float4*)(Abase + ((ks+1)*16 + kkSa)*HW + r4*4);
      vw0 = *(const float4*)(W1 + ((ks+1)*16 + kkSw)*DM + c4*4);
      vw1 = *(const float4*)(W1 + ((ks+1)*16 + 8 + kkSw)*DM + c4*4);
    }
    __syncthreads();
    if (ks < 15){
      uint32_t bo = (uint32_t)(((ks+1) & 1));
      uint32_t h0,l0,h1,l1;
      split2(va.x, va.y, h0, l0); split2(va.z, va.w, h1, l1);
      sts64(ah0 + bo*2048 + aSaddr, h0, h1);
      sts64(al0 + bo*2048 + aSaddr, l0, l1);
      split2(vw0.x, vw0.y, h0, l0); split2(vw0.z, vw0.w, h1, l1);
      sts64(wh0 + bo*4096 + wSaddr0, h0, h1);
      sts64(wl0 + bo*4096 + wSaddr0, l0, l1);
      split2(vw1.x, vw1.y, h0, l0); split2(vw1.z, vw1.w, h1, l1);
      sts64(wh0 + bo*4096 + wSaddr1, h0, h1);
      sts64(wl0 + bo*4096 + wSaddr1, l0, l1);
    }

    uint32_t cu = (uint32_t)(ks & 1);
    uint32_t ah[4], al[4];
    ldsm4t(ah0 + cu*2048 + aoff, ah);
    ldsm4t(al0 + cu*2048 + aoff, al);

    #pragma unroll
    for (int p=0; p<4; p++){
      int unit = nbase8 + 2*p + nsel;
      uint32_t waddr = cu*4096 + (uint32_t)(kkW*256 + ((unit ^ (kkW & 7)))*16);
      uint32_t wh[4], wl[4];
      ldsm4t(wh0 + waddr, wh);
      ldsm4t(wl0 + waddr, wl);
      mma_bf16(oa[2*p],   ah, wh[0], wh[1]);
      mma_bf16(oa[2*p],   ah, wl[0], wl[1]);
      mma_bf16(oa[2*p],   al, wh[0], wh[1]);
      mma_bf16(oa[2*p+1], ah, wh[2], wh[3]);
      mma_bf16(oa[2*p+1], ah, wl[2], wl[3]);
      mma_bf16(oa[2*p+1], al, wh[2], wh[3]);
    }
  }
  __syncthreads();

  {
    int r0 = (w & 3)*16 + gid;
    #pragma unroll
    for (int p=0; p<8; p++){
      int c0 = (w >> 2)*64 + p*8 + 2*tig;
      sOut[r0*132 + c0]       = oa[p][0];
      sOut[r0*132 + c0 + 1]   = oa[p][1];
      sOut[(r0+8)*132 + c0]   = oa[p][2];
      sOut[(r0+8)*132 + c0+1] = oa[p][3];
    }
  }
  __syncthreads();

  {
    int r = tid >> 2, seg = tid & 3;
    float xv[32];
    float s = 0.f;
    float* op = sOut + r*132 + seg*32;
    const float* bp = b1 + seg*32;
    #pragma unroll
    for (int j4=0; j4<8; j4++){
      float4 xb = *(float4*)(op + j4*4);
      float4 bb = *(const float4*)(bp + j4*4);
      float x0 = xb.x + bb.x, x1 = xb.y + bb.y, x2 = xb.z + bb.z, x3 = xb.w + bb.w;
      xv[4*j4]=x0; xv[4*j4+1]=x1; xv[4*j4+2]=x2; xv[4*j4+3]=x3;
      s += x0*x0 + x1*x1 + x2*x2 + x3*x3;
    }
    s += __shfl_xor_sync(0xffffffffu, s, 1);
    s += __shfl_xor_sync(0xffffffffu, s, 2);
    float inv = 1.0f / fmaxf(sqrtf(s), 1e-12f);
    float* tp = g_tok + (size_t)(tile*64 + r)*DM + seg*32;
    #pragma unroll
    for (int j4=0; j4<8; j4++){
      float4 o = make_float4(xv[4*j4]*inv, xv[4*j4+1]*inv, xv[4*j4+2]*inv, xv[4*j4+3]*inv);
      *(float4*)(tp + j4*4) = o;
      *(float4*)(op + j4*4) = o;
    }
  }
  __syncthreads();

  if (tid < 128){
    float cs = 0.f;
    #pragma unroll 8
    for (int r=0; r<64; r++) cs += sOut[r*132 + tid];
    atomicAdd(&g_m0[b*DM + tid], cs);
  }
}

// ---------------- K3: attention, 128-key tiles, deg-2 expm1, mma-l -----------
// u = t(1 + t/2); PV and l both via tensor core; l from bf16 u (consistent
// with PV weights). No epilogue shuffles.
__global__ __launch_bounds__(256) void attn_bf16_kernel(){
  __shared__ __align__(1024) unsigned char sbuf[2][4096];
  int b = blockIdx.z, h = blockIdx.y;
  int tid = threadIdx.x, w = tid >> 5, lane = tid & 31;
  int gid = lane >> 2, tig = lane & 3, r7 = lane & 7;
  const float* base = g_tok + b*HW*DM + h*DH;
  int qb0 = blockIdx.x*128 + w*16;
  bool wstore = (qb0 < HW);
  int qbase = wstore ? qb0 : (HW - 16);

  uint32_t qh[4];
  #pragma unroll
  for (int i=0;i<4;i++){
    int row = qbase + gid + (i & 1)*8;
    int col = 2*tig + (i >> 1)*8;
    float2 v = *(const float2*)(base + row*DM + col);
    qh[i] = packbf(__float2bfloat16_rn(v.x*0.25f), __float2bfloat16_rn(v.y*0.25f));
  }

  float oa0E[4] = {0.f,0.f,0.f,0.f};
  float oa1E[4] = {0.f,0.f,0.f,0.f};
  float oa0O[4] = {0.f,0.f,0.f,0.f};
  float oa1O[4] = {0.f,0.f,0.f,0.f};
  float lsE[4]  = {0.f,0.f,0.f,0.f};
  float lsO[4]  = {0.f,0.f,0.f,0.f};

  const u64 CH  = pack2(0.5f, 0.5f);
  const u64 C1  = pack2(1.0f, 1.0f);
  const uint32_t ONES = 0x3F803F80u;   // bf16x2 {1.0, 1.0}

  uint32_t sb0 = (uint32_t)__cvta_generic_to_shared(&sbuf[0][0]);
  uint32_t aScore = sb0 + (uint32_t)((r7 + ((lane >> 4) & 1)*8)*16 + ((lane >> 3) & 1)*2048);
  uint32_t aPV    = sb0 + (uint32_t)((r7 + ((lane >> 3) & 1)*8)*16 + ((lane >> 4) & 1)*2048);

  int key0 = tid >> 2, quarter = tid & 3;
  const float* g0 = base + key0*DM + quarter*4;
  const float* g1 = g0 + 64*DM;
  uint32_t dst0 = sb0 + (uint32_t)((quarter >> 1)*2048 + key0*16 + (quarter & 1)*8);
  uint32_t dst1 = dst0 + 64*16;

  {
    float4 v0 = *(const float4*)(g0);
    float4 v1 = *(const float4*)(g1);
    sts64(dst0, cvt_bf16x2_ff(v0.x, v0.y), cvt_bf16x2_ff(v0.z, v0.w));
    sts64(dst1, cvt_bf16x2_ff(v1.x, v1.y), cvt_bf16x2_ff(v1.z, v1.w));
  }
  __syncthreads();

  for (int kb=0; kb<13; kb++){
    float4 nv0, nv1;
    if (kb < 12){
      nv0 = *(const float4*)(g0 + (kb+1)*128*DM);
      int gk1 = (kb+1)*128 + key0 + 64;
      if (gk1 < HW) nv1 = *(const float4*)(g1 + (kb+1)*128*DM);
      else          nv1 = make_float4(0.f, 0.f, 0.f, 0.f);  // zero keys: u=0, exp-neutral
    }
    uint32_t bufoff = (uint32_t)((kb & 1)*4096);
    uint32_t aS = aScore + bufoff;
    uint32_t aP = aPV + bufoff;

    #pragma unroll
    for (int ck=0; ck<8; ck++){
      uint32_t off = (uint32_t)(ck*256);
      uint32_t kh[4], vv[4];
      ldsm4 (aS + off, kh);
      ldsm4t(aP + off, vv);

      float cA[4] = {0.f,0.f,0.f,0.f};
      float cB[4] = {0.f,0.f,0.f,0.f};
      mma_bf16(cA, qh, kh[0], kh[1]);
      mma_bf16(cB, qh, kh[2], kh[3]);

      // u = expm1(t) deg-2: u = t*(1 + t/2), packed pairs
      u64 tA01 = pack2(cA[0], cA[1]);
      u64 tA23 = pack2(cA[2], cA[3]);
      u64 tB01 = pack2(cB[0], cB[1]);
      u64 tB23 = pack2(cB[2], cB[3]);
      u64 wA01 = fma2(tA01, CH, C1);
      u64 wA23 = fma2(tA23, CH, C1);
      u64 wB01 = fma2(tB01, CH, C1);
      u64 wB23 = fma2(tB23, CH, C1);
      u64 uA01 = mul2(tA01, wA01);
      u64 uA23 = mul2(tA23, wA23);
      u64 uB01 = mul2(tB01, wB01);
      u64 uB23 = mul2(tB23, wB23);

      uint32_t pa[4];
      pa[0] = cvt_bf16x2(uA01);
      pa[1] = cvt_bf16x2(uA23);
      pa[2] = cvt_bf16x2(uB01);
      pa[3] = cvt_bf16x2(uB23);

      if (ck & 1){
        mma_bf16(oa0O, pa, vv[0], vv[1]);
        mma_bf16(oa1O, pa, vv[2], vv[3]);
        mma_bf16(lsO,  pa, ONES,  ONES);   // row sums of u -> denominator
      } else {
        mma_bf16(oa0E, pa, vv[0], vv[1]);
        mma_bf16(oa1E, pa, vv[2], vv[3]);
        mma_bf16(lsE,  pa, ONES,  ONES);
      }
    }

    if (kb < 12){
      uint32_t d = (uint32_t)(((kb+1) & 1)*4096);
      sts64(dst0 + d, cvt_bf16x2_ff(nv0.x, nv0.y), cvt_bf16x2_ff(nv0.z, nv0.w));
      sts64(dst1 + d, cvt_bf16x2_ff(nv1.x, nv1.y), cvt_bf16x2_ff(nv1.z, nv1.w));
    }
    __syncthreads();
  }

  float oa0[4], oa1[4];
  #pragma unroll
  for (int i=0;i<4;i++){ oa0[i] = oa0E[i] + oa0O[i]; oa1[i] = oa1E[i] + oa1O[i]; }
  // ls[0](=ls[1]) = row sum for query gid; ls[2](=ls[3]) = query gid+8. No shuffles.
  float inv0 = 1.0f / (1600.0f + (lsE[0] + lsO[0]));
  float inv8 = 1.0f / (1600.0f + (lsE[2] + lsO[2]));

  if (wstore){
    const float* m0p = g_m0 + b*DM + h*DH;
    float* outb = g_attn + (b*HW + qbase)*DM + h*DH;
    float* oas[2] = {oa0, oa1};
    #pragma unroll
    for (int nt=0; nt<2; nt++){
      int d0 = nt*8 + 2*tig;
      float m0a = m0p[d0], m0b = m0p[d0+1];
      outb[(gid  )*DM + d0    ] = (oas[nt][0] + m0a) * inv0;
      outb[(gid  )*DM + d0 + 1] = (oas[nt][1] + m0b) * inv0;
      outb[(gid+8)*DM + d0    ] = (oas[nt][2] + m0a) * inv8;
      outb[(gid+8)*DM + d0 + 1] = (oas[nt][3] + m0b) * inv8;
    }
  }
}

// ---------------- K4: gemm2 split-bf16 mma, 32-row tiles, 3 CTAs/SM ----------
__global__ __launch_bounds__(256, 3) void gemm2_mma_kernel(const float* __restrict__ W2,
                                                           const float* __restrict__ b2,
                                                           float* __restrict__ img_out){
  __shared__ __align__(1024) unsigned char sA[2][8192];
  __shared__ __align__(1024) unsigned char sW[2][8192];
  int tile = blockIdx.x;
  int b = tile / 50, pbase = (tile % 50) * 32;
  int tid = threadIdx.x, w = tid >> 5, lane = tid & 31;
  int gid = lane >> 2, tig = lane & 3, r7 = lane & 7;

  uint32_t sa0 = (uint32_t)__cvta_generic_to_shared(&sA[0][0]);
  uint32_t sw0 = (uint32_t)__cvta_generic_to_shared(&sW[0][0]);

  {
    const float* Abase = g_attn + (size_t)(tile*32)*DM;
    #pragma unroll
    for (int it=0; it<4; it++){
      int idx = tid + it*256;
      int r = idx >> 5, kc4 = idx & 31;
      int kc = kc4 >> 1, half = kc4 & 1;
      float4 v = *(const float4*)(Abase + r*DM + kc4*4);
      uint32_t h0, l0, h1, l1;
      split2(v.x, v.y, h0, l0);
      split2(v.z, v.w, h1, l1);
      uint32_t addr = sa0 + (uint32_t)(r*256 + ((kc ^ (r & 7)))*16 + half*8);
      sts64(addr,        h0, h1);
      sts64(addr + 8192, l0, l1);
    }
  }

  float oa[8][4];
  #pragma unroll
  for (int i=0;i<8;i++){ oa[i][0]=0.f; oa[i][1]=0.f; oa[i][2]=0.f; oa[i][3]=0.f; }

  int arow = (w & 1)*16 + r7 + ((lane >> 3) & 1)*8;
  int klocal = r7 + ((lane >> 3) & 1)*8;
  int ncsel  = (lane >> 4) & 1;
  int nbase  = (w >> 1) * 8;

  for (int ks=0; ks<8; ks++){
    __syncthreads();
    #pragma unroll
    for (int it=0; it<4; it++){
      int idx = tid + it*256;
      int kk = idx >> 6, nc4 = idx & 63;
      float4 v = *(const float4*)(W2 + (ks*16 + kk)*CI + nc4*4);
      int nc = nc4 >> 1, half = nc4 & 1;
      uint32_t h0, l0, h1, l1;
      split2(v.x, v.y, h0, l0);
      split2(v.z, v.w, h1, l1);
      uint32_t addr = sw0 + (uint32_t)(kk*512 + (nc ^ (kk & 7))*16 + half*8);
      sts64(addr,        h0, h1);
      sts64(addr + 8192, l0, l1);
    }
    __syncthreads();

    uint32_t ah[4], al[4];
    {
      int kcv = 2*ks + ((lane >> 4) & 1);
      uint32_t aaddr = sa0 + (uint32_t)(arow*256 + ((kcv ^ r7))*16);
      ldsm4(aaddr, ah);
      ldsm4(aaddr + 8192, al);
    }

    #pragma unroll
    for (int p=0; p<4; p++){
      int nc0 = nbase + 2*p;
      uint32_t waddr = sw0 + (uint32_t)(klocal*512 + (((nc0 + ncsel) ^ r7))*16);
      uint32_t wh[4], wl[4];
      ldsm4t(waddr, wh);
      ldsm4t(waddr + 8192, wl);
      mma_bf16(oa[2*p],   ah, wh[0], wh[1]);
      mma_bf16(oa[2*p],   ah, wl[0], wl[1]);
      mma_bf16(oa[2*p],   al, wh[0], wh[1]);
      mma_bf16(oa[2*p+1], ah, wh[2], wh[3]);
      mma_bf16(oa[2*p+1], ah, wl[2], wl[3]);
      mma_bf16(oa[2*p+1], al, wh[2], wh[3]);
    }
  }

  int p0 = pbase + (w & 1)*16 + gid;
  float* outB = img_out + (size_t)b*CI*HW;
  #pragma unroll
  for (int nc=0; nc<8; nc++){
    int c0 = (w >> 1)*64 + nc*8 + 2*tig;
    float bb0 = __ldg(b2 + c0), bb1 = __ldg(b2 + c0 + 1);
    float v00 = oa[nc][0] + bb0, v01 = oa[nc][1] + bb1;
    float v10 = oa[nc][2] + bb0, v11 = oa[nc][3] + bb1;
    outB[(size_t)c0*HW + p0]           = v00;
    outB[(size_t)(c0+1)*HW + p0]       = v01;
    outB[(size_t)c0*HW + p0 + 8]       = v10;
    outB[(size_t)(c0+1)*HW + p0 + 8]   = v11;
    float e00 = fmaxf(v00, 1e-6f), e01 = fmaxf(v01, 1e-6f);
    float e10 = fmaxf(v10, 1e-6f), e11 = fmaxf(v11, 1e-6f);
    float pc0 = e00*e00*e00 + e10*e10*e10;
    float pc1 = e01*e01*e01 + e11*e11*e11;
    pc0 += __shfl_xor_sync(0xffffffffu, pc0, 4);
    pc1 += __shfl_xor_sync(0xffffffffu, pc1, 4);
    pc0 += __shfl_xor_sync(0xffffffffu, pc0, 8);
    pc1 += __shfl_xor_sync(0xffffffffu, pc1, 8);
    pc0 += __shfl_xor_sync(0xffffffffu, pc0, 16);
    pc1 += __shfl_xor_sync(0xffffffffu, pc1, 16);
    if (lane < 4){
      atomicAdd(&g_imgacc[b*CI + c0],     pc0);
      atomicAdd(&g_imgacc[b*CI + c0 + 1], pc1);
    }
  }
}

// ---------------- K7: cloud l2norm + segmented clamp^3 sum -------------------
__global__ __launch_bounds__(256) void cloud_kernel(const float* __restrict__ cf,
                                                    const int* __restrict__ bids,
                                                    float* __restrict__ cloud_out){
  __shared__ float sseg[NB*DM];
  __shared__ float scnt[NB];
  int tid = threadIdx.x;
  for (int i=tid; i<NB*DM; i+=256) sseg[i] = 0.f;
  if (tid < NB) scnt[tid] = 0.f;
  __syncthreads();
  int w = tid >> 5, lane = tid & 31;
  int rbase = blockIdx.x*64 + w*8;
  #pragma unroll
  for (int i=0;i<8;i++){
    int row = rbase + i;
    int bid = bids[row];
    float4 v = *(const float4*)(cf + row*DM + lane*4);
    float sq = v.x*v.x + v.y*v.y + v.z*v.z + v.w*v.w;
    #pragma unroll
    for (int off=16; off; off>>=1) sq += __shfl_xor_sync(0xffffffffu, sq, off);
    float inv = 1.0f / fmaxf(sqrtf(sq), 1e-12f);
    float x0=v.x*inv, x1=v.y*inv, x2=v.z*inv, x3=v.w*inv;
    *(float4*)(cloud_out + row*DM + lane*4) = make_float4(x0,x1,x2,x3);
    float c0=fmaxf(x0,1e-6f), c1=fmaxf(x1,1e-6f), c2=fmaxf(x2,1e-6f), c3=fmaxf(x3,1e-6f);
    float* sp = sseg + bid*DM + lane*4;
    atomicAdd(sp+0, c0*c0*c0);
    atomicAdd(sp+1, c1*c1*c1);
    atomicAdd(sp+2, c2*c2*c2);
    atomicAdd(sp+3, c3*c3*c3);
    if (lane == 0) atomicAdd(&scnt[bid], 1.0f);
  }
  __syncthreads();
  for (int i=tid; i<NB*DM; i+=256) atomicAdd(&g_seg[i], sseg[i]);
  if (tid < NB) atomicAdd(&g_cnt[tid], scnt[tid]);
}

// ---------------- K8: finalize GeM outputs ----------------
__global__ void finalize_kernel(float* __restrict__ image_gem, float* __restrict__ cloud_gem){
  int i = blockIdx.x*256 + threadIdx.x;
  if (i < NB*CI) image_gem[i] = cbrtf(g_imgacc[i] * (1.0f/1600.0f));
  if (i < NB*DM) cloud_gem[i] = cbrtf(g_seg[i] / fmaxf(g_cnt[i>>7], 1.0f));
}

// ---------------- launch ----------------
extern "C" void kernel_launch(void* const* d_in, const int* in_sizes, int n_in,
                              void* d_out, int out_size){
  const float* img  = (const float*)d_in[0];
  const float* cf   = (const float*)d_in[1];
  const int*   bids = (const int*)  d_in[2];
  const float* W1   = (const float*)d_in[3];
  const float* b1   = (const float*)d_in[4];
  const float* W2   = (const float*)d_in[5];
  const float* b2   = (const float*)d_in[6];

  float* out       = (float*)d_out;
  float* img_out   = out;                                  // 8*256*1600
  float* cloud_out = out + (size_t)NB*CI*HW;               // 32768*128
  float* image_gem = cloud_out + (size_t)NCLOUD*DM;        // 2048
  float* cloud_gem = image_gem + NB*CI;                    // 1024

  zero_kernel<<<8, 256>>>();
  gemm1_mma_kernel<<<200, 256>>>(img, W1, b1);
  attn_bf16_kernel<<<dim3(13, NHEAD, NB), 256>>>();
  gemm2_mma_kernel<<<400, 256>>>(W2, b2, img_out);
  cloud_kernel<<<512, 256>>>(cf, bids, cloud_out);
  finalize_kernel<<<8, 256>>>(image_gem, cloud_gem);
}